// round 4
// baseline (speedup 1.0000x reference)
#include <cuda_runtime.h>
#include <cuda_bf16.h>
#include <math.h>
#include <stdint.h>

// Problem dims (fixed)
#define BB 8
#define LL 2048
#define EE 1024
#define HH 16
#define DD 64
#define MM (BB*LL)      // 16384 rows
#define FF (4*EE)       // 4096 ffn dim

#define LN_EPS 1e-5f
#define ATTN_EPS 1e-6f

// ======================= helpers =======================
__device__ __forceinline__ uint32_t smem_to_u32(const void* smem_ptr) {
    uint32_t addr;
    asm("{ .reg .u64 tmp; cvta.to.shared.u64 tmp, %1; cvt.u32.u64 %0, tmp; }"
        : "=r"(addr) : "l"(smem_ptr));
    return addr;
}

__device__ __forceinline__ void cp_async16(uint32_t saddr, const void* gptr) {
    asm volatile("cp.async.cg.shared.global [%0], [%1], 16;" :: "r"(saddr), "l"(gptr));
}
__device__ __forceinline__ void cp_commit() {
    asm volatile("cp.async.commit_group;");
}
template<int N>
__device__ __forceinline__ void cp_wait() {
    asm volatile("cp.async.wait_group %0;" :: "n"(N));
}

__device__ __forceinline__ void ldmatrix_x4(uint32_t* r, uint32_t addr) {
    asm volatile("ldmatrix.sync.aligned.m8n8.x4.shared.b16 {%0,%1,%2,%3}, [%4];"
                 : "=r"(r[0]), "=r"(r[1]), "=r"(r[2]), "=r"(r[3]) : "r"(addr));
}

__device__ __forceinline__ void mma16816(float* c, const uint32_t* a, uint32_t b0, uint32_t b1) {
    asm volatile(
        "mma.sync.aligned.m16n8k16.row.col.f32.bf16.bf16.f32 "
        "{%0,%1,%2,%3}, {%4,%5,%6,%7}, {%8,%9}, {%0,%1,%2,%3};"
        : "+f"(c[0]), "+f"(c[1]), "+f"(c[2]), "+f"(c[3])
        : "r"(a[0]), "r"(a[1]), "r"(a[2]), "r"(a[3]), "r"(b0), "r"(b1));
}

// ======================= scratch (device globals) =======================
__device__ __align__(256) __nv_bfloat16 g_hhi [(size_t)MM * EE];
__device__ __align__(256) __nv_bfloat16 g_hlo [(size_t)MM * EE];
__device__ __align__(256) __nv_bfloat16 g_aohi[(size_t)MM * EE];
__device__ __align__(256) __nv_bfloat16 g_aolo[(size_t)MM * EE];
__device__ __align__(256) __nv_bfloat16 g_f1hi[(size_t)MM * FF];
__device__ __align__(256) __nv_bfloat16 g_f1lo[(size_t)MM * FF];
__device__ __align__(256) float g_q [(size_t)MM * EE];
__device__ __align__(256) float g_k [(size_t)MM * EE];
__device__ __align__(256) float g_v [(size_t)MM * EE];
__device__ __align__(256) float g_x2[(size_t)MM * EE];
__device__ __align__(256) __nv_bfloat16 g_wqhi[(size_t)EE*EE], g_wqlo[(size_t)EE*EE];
__device__ __align__(256) __nv_bfloat16 g_wkhi[(size_t)EE*EE], g_wklo[(size_t)EE*EE];
__device__ __align__(256) __nv_bfloat16 g_wvhi[(size_t)EE*EE], g_wvlo[(size_t)EE*EE];
__device__ __align__(256) __nv_bfloat16 g_wohi[(size_t)EE*EE], g_wolo[(size_t)EE*EE];
__device__ __align__(256) __nv_bfloat16 g_w1hi[(size_t)FF*EE], g_w1lo[(size_t)FF*EE];
__device__ __align__(256) __nv_bfloat16 g_w2hi[(size_t)EE*FF], g_w2lo[(size_t)EE*FF];
__device__ __align__(256) float g_kvp[4 * BB * HH * DD * DD]; // partial KV
__device__ __align__(256) float g_ksp[4 * BB * HH * DD];      // partial Ksum

// ======================= fused fp32 -> bf16 hi/lo weight conversion =======================
#define NE4 (EE*EE/4)
#define NF4 (EE*FF/4)
__global__ void cvt_all_kernel(
    const float* __restrict__ Wq, const float* __restrict__ Wk,
    const float* __restrict__ Wv, const float* __restrict__ Wo,
    const float* __restrict__ W1, const float* __restrict__ W2,
    __nv_bfloat16* __restrict__ qh, __nv_bfloat16* __restrict__ ql,
    __nv_bfloat16* __restrict__ kh, __nv_bfloat16* __restrict__ kl,
    __nv_bfloat16* __restrict__ vh, __nv_bfloat16* __restrict__ vl,
    __nv_bfloat16* __restrict__ oh, __nv_bfloat16* __restrict__ ol,
    __nv_bfloat16* __restrict__ f1h, __nv_bfloat16* __restrict__ f1l,
    __nv_bfloat16* __restrict__ f2h, __nv_bfloat16* __restrict__ f2l)
{
    int i = blockIdx.x * 256 + threadIdx.x;
    const float* s; __nv_bfloat16 *hi, *lo; int off;
    if (i < 4 * NE4) {
        int w = i / NE4; off = i - w * NE4;
        s  = (w == 0) ? Wq : (w == 1) ? Wk : (w == 2) ? Wv : Wo;
        hi = (w == 0) ? qh : (w == 1) ? kh : (w == 2) ? vh : oh;
        lo = (w == 0) ? ql : (w == 1) ? kl : (w == 2) ? vl : ol;
    } else {
        int j = i - 4 * NE4;
        int w = j / NF4; off = j - w * NF4;
        s  = (w == 0) ? W1 : W2;
        hi = (w == 0) ? f1h : f2h;
        lo = (w == 0) ? f1l : f2l;
    }
    float4 v = ((const float4*)s)[off];
    __nv_bfloat16 h0 = __float2bfloat16(v.x), h1 = __float2bfloat16(v.y);
    __nv_bfloat16 h2 = __float2bfloat16(v.z), h3 = __float2bfloat16(v.w);
    ((__nv_bfloat162*)hi)[2*off]   = __halves2bfloat162(h0, h1);
    ((__nv_bfloat162*)hi)[2*off+1] = __halves2bfloat162(h2, h3);
    ((__nv_bfloat162*)lo)[2*off]   = __halves2bfloat162(
        __float2bfloat16(v.x - __bfloat162float(h0)),
        __float2bfloat16(v.y - __bfloat162float(h1)));
    ((__nv_bfloat162*)lo)[2*off+1] = __halves2bfloat162(
        __float2bfloat16(v.z - __bfloat162float(h2)),
        __float2bfloat16(v.w - __bfloat162float(h3)));
}

// ======================= LayerNorm (writes bf16 hi/lo) =======================
__global__ void ln_hilo_kernel(const float* __restrict__ x,
                               const float* __restrict__ g,
                               const float* __restrict__ b,
                               __nv_bfloat16* __restrict__ yhi,
                               __nv_bfloat16* __restrict__ ylo)
{
    const int row = blockIdx.x;
    const int tid = threadIdx.x;
    const float4* xr = (const float4*)(x + (size_t)row * EE);
    float4 v = xr[tid];
    float s  = v.x + v.y + v.z + v.w;
    float sq = v.x*v.x + v.y*v.y + v.z*v.z + v.w*v.w;

    #pragma unroll
    for (int off = 16; off > 0; off >>= 1) {
        s  += __shfl_xor_sync(0xffffffffu, s,  off);
        sq += __shfl_xor_sync(0xffffffffu, sq, off);
    }
    __shared__ float ws[8], wsq[8];
    __shared__ float s_mean, s_rstd;
    const int wid = tid >> 5, lane = tid & 31;
    if (lane == 0) { ws[wid] = s; wsq[wid] = sq; }
    __syncthreads();
    if (tid == 0) {
        float ts = 0.f, tsq = 0.f;
        #pragma unroll
        for (int i = 0; i < 8; i++) { ts += ws[i]; tsq += wsq[i]; }
        float mean = ts * (1.0f / EE);
        float var  = tsq * (1.0f / EE) - mean * mean;
        s_mean = mean;
        s_rstd = rsqrtf(var + LN_EPS);
    }
    __syncthreads();
    const float mean = s_mean, rstd = s_rstd;
    float4 gg = ((const float4*)g)[tid];
    float4 bb = ((const float4*)b)[tid];
    float o0 = (v.x - mean) * rstd * gg.x + bb.x;
    float o1 = (v.y - mean) * rstd * gg.y + bb.y;
    float o2 = (v.z - mean) * rstd * gg.z + bb.z;
    float o3 = (v.w - mean) * rstd * gg.w + bb.w;
    __nv_bfloat16 h0 = __float2bfloat16(o0), h1 = __float2bfloat16(o1);
    __nv_bfloat16 h2 = __float2bfloat16(o2), h3 = __float2bfloat16(o3);
    __nv_bfloat162* hp = (__nv_bfloat162*)(yhi + (size_t)row * EE + tid * 4);
    __nv_bfloat162* lp = (__nv_bfloat162*)(ylo + (size_t)row * EE + tid * 4);
    hp[0] = __halves2bfloat162(h0, h1);
    hp[1] = __halves2bfloat162(h2, h3);
    lp[0] = __halves2bfloat162(__float2bfloat16(o0 - __bfloat162float(h0)),
                               __float2bfloat16(o1 - __bfloat162float(h1)));
    lp[1] = __halves2bfloat162(__float2bfloat16(o2 - __bfloat162float(h2)),
                               __float2bfloat16(o3 - __bfloat162float(h3)));
}

// ======================= GEMM core: CTA 128x256, 8 warps 64x64, 3-stage =======================
#define Bb_K 32
#define STAGE_BYTES 49152
#define OFF_AHI 0
#define OFF_ALO 8192
#define OFF_BHI 16384
#define OFF_BLO 32768
#define GEMM_SMEM (3*STAGE_BYTES)

__device__ __forceinline__ uint32_t swz(int row, int c) {
    return (uint32_t)(row * 64 + ((c ^ ((row >> 1) & 3)) << 4));
}

// Shared mainloop body via macro-free structure: generic and QKV kernels duplicate it.

template<int EPI, int OUT>   // EPI: 0 none, 2 relu, 3 +residual ; OUT: 0 fp32, 1 bf16 hi/lo
__global__ void __launch_bounds__(256)
gemm3bf(const __nv_bfloat16* __restrict__ Ahi, const __nv_bfloat16* __restrict__ Alo,
        const __nv_bfloat16* __restrict__ Bhi, const __nv_bfloat16* __restrict__ Blo,
        const float* __restrict__ bias, const float* __restrict__ Rres,
        float* __restrict__ Cf, __nv_bfloat16* __restrict__ Chi,
        __nv_bfloat16* __restrict__ Clo,
        int M, int N, int K)
{
    extern __shared__ __align__(128) char smem[];
    const uint32_t smem_u = smem_to_u32(smem);

    const int tid = threadIdx.x;
    const int wid = tid >> 5, lane = tid & 31;
    const int bm = blockIdx.y, bn = blockIdx.x;
    const int warp_m = (wid >> 2) * 64;
    const int warp_n = (wid & 3) * 64;

    const __nv_bfloat16* gAhi = Ahi + (size_t)(bm * 128) * K;
    const __nv_bfloat16* gAlo = Alo + (size_t)(bm * 128) * K;
    const __nv_bfloat16* gBhi = Bhi + (size_t)(bn * 256) * K;
    const __nv_bfloat16* gBlo = Blo + (size_t)(bn * 256) * K;

    const int nc = K >> 5;
    const int lrow = tid >> 2, lc = tid & 3;

    auto issue_stage = [&](int c) {
        if (c < nc) {
            const uint32_t sb = smem_u + (c % 3) * STAGE_BYTES;
            const int k0 = c * 32;
            #pragma unroll
            for (int i = 0; i < 2; i++) {          // A: 128 rows
                const int row = lrow + i * 64;
                const uint32_t so = swz(row, lc);
                const size_t go = (size_t)row * K + k0 + lc * 8;
                cp_async16(sb + OFF_AHI + so, gAhi + go);
                cp_async16(sb + OFF_ALO + so, gAlo + go);
            }
            #pragma unroll
            for (int i = 0; i < 4; i++) {          // B: 256 rows
                const int row = lrow + i * 64;
                const uint32_t so = swz(row, lc);
                const size_t go = (size_t)row * K + k0 + lc * 8;
                cp_async16(sb + OFF_BHI + so, gBhi + go);
                cp_async16(sb + OFF_BLO + so, gBlo + go);
            }
        }
        cp_commit();
    };

    float acc[4][8][4];
    #pragma unroll
    for (int i = 0; i < 4; i++)
        #pragma unroll
        for (int j = 0; j < 8; j++)
            #pragma unroll
            for (int t = 0; t < 4; t++) acc[i][j][t] = 0.f;

    issue_stage(0); issue_stage(1);

    const int lm_r = ((lane >> 3) & 1) * 8 + (lane & 7);
    const int lm_c = lane >> 4;

    for (int c = 0; c < nc; c++) {
        cp_wait<1>();
        __syncthreads();
        issue_stage(c + 2);                 // writes stage (c-1)%3: readers done at sync
        const uint32_t sb = smem_u + (c % 3) * STAGE_BYTES;

        #pragma unroll
        for (int s = 0; s < 2; s++) {
            const int chunk = 2 * s + lm_c;
            uint32_t Bh[4][4], Bl[4][4];
            #pragma unroll
            for (int p = 0; p < 4; p++) {
                const int row = warp_n + p * 16 + lm_r;
                const uint32_t a = sb + OFF_BHI + swz(row, chunk);
                ldmatrix_x4(Bh[p], a);
                ldmatrix_x4(Bl[p], a + (OFF_BLO - OFF_BHI));
            }
            #pragma unroll
            for (int mi = 0; mi < 4; mi++) {
                const int row = warp_m + mi * 16 + lm_r;
                uint32_t Ah[4], Al[4];
                const uint32_t a = sb + OFF_AHI + swz(row, chunk);
                ldmatrix_x4(Ah, a);
                ldmatrix_x4(Al, a + (OFF_ALO - OFF_AHI));
                #pragma unroll
                for (int ni = 0; ni < 8; ni++) {
                    const int p = ni >> 1, q = ni & 1;
                    mma16816(acc[mi][ni], Ah, Bh[p][q], Bh[p][2 + q]);
                    mma16816(acc[mi][ni], Ah, Bl[p][q], Bl[p][2 + q]);
                    mma16816(acc[mi][ni], Al, Bh[p][q], Bh[p][2 + q]);
                }
            }
        }
    }

    // ---------------- epilogue ----------------
    const int g = lane >> 2, tig = lane & 3;
    #pragma unroll
    for (int ni = 0; ni < 8; ni++) {
        const int n = bn * 256 + warp_n + ni * 8 + tig * 2;
        const float b0 = __ldg(bias + n), b1 = __ldg(bias + n + 1);
        #pragma unroll
        for (int mi = 0; mi < 4; mi++) {
            const int m0 = bm * 128 + warp_m + mi * 16 + g;
            #pragma unroll
            for (int half = 0; half < 2; half++) {
                const int m = m0 + half * 8;
                float v0 = acc[mi][ni][half * 2 + 0] + b0;
                float v1 = acc[mi][ni][half * 2 + 1] + b1;
                if (EPI == 2) { v0 = fmaxf(v0, 0.f); v1 = fmaxf(v1, 0.f); }
                else if (EPI == 3) {
                    const float2 rv = *(const float2*)(Rres + (size_t)m * N + n);
                    v0 += rv.x; v1 += rv.y;
                }
                if (OUT == 0) {
                    *(float2*)(Cf + (size_t)m * N + n) = make_float2(v0, v1);
                } else {
                    __nv_bfloat16 h0 = __float2bfloat16(v0);
                    __nv_bfloat16 h1 = __float2bfloat16(v1);
                    *(__nv_bfloat162*)(Chi + (size_t)m * N + n) = __halves2bfloat162(h0, h1);
                    *(__nv_bfloat162*)(Clo + (size_t)m * N + n) = __halves2bfloat162(
                        __float2bfloat16(v0 - __bfloat162float(h0)),
                        __float2bfloat16(v1 - __bfloat162float(h1)));
                }
            }
        }
    }
}

// ---- fused QKV GEMM: bn in [0,12); w = bn>>2 selects Wq/Wk/Wv; elu+1 on q,k ----
__global__ void __launch_bounds__(256)
gemm_qkv(const __nv_bfloat16* __restrict__ Ahi, const __nv_bfloat16* __restrict__ Alo,
         const __nv_bfloat16* __restrict__ wqh, const __nv_bfloat16* __restrict__ wql,
         const __nv_bfloat16* __restrict__ wkh, const __nv_bfloat16* __restrict__ wkl,
         const __nv_bfloat16* __restrict__ wvh, const __nv_bfloat16* __restrict__ wvl,
         const float* __restrict__ bq, const float* __restrict__ bk,
         const float* __restrict__ bv,
         float* __restrict__ oq, float* __restrict__ ok, float* __restrict__ ov)
{
    extern __shared__ __align__(128) char smem[];
    const uint32_t smem_u = smem_to_u32(smem);
    const int K = EE, N = EE;

    const int tid = threadIdx.x;
    const int wid = tid >> 5, lane = tid & 31;
    const int bm = blockIdx.y, bnL = blockIdx.x;
    const int w = bnL >> 2, bn = bnL & 3;
    const int warp_m = (wid >> 2) * 64;
    const int warp_n = (wid & 3) * 64;

    const __nv_bfloat16* Bhi = (w == 0) ? wqh : (w == 1) ? wkh : wvh;
    const __nv_bfloat16* Blo = (w == 0) ? wql : (w == 1) ? wkl : wvl;
    const float* bias = (w == 0) ? bq : (w == 1) ? bk : bv;
    float* Cf = (w == 0) ? oq : (w == 1) ? ok : ov;
    const bool do_elu = (w < 2);

    const __nv_bfloat16* gAhi = Ahi + (size_t)(bm * 128) * K;
    const __nv_bfloat16* gAlo = Alo + (size_t)(bm * 128) * K;
    const __nv_bfloat16* gBhi = Bhi + (size_t)(bn * 256) * K;
    const __nv_bfloat16* gBlo = Blo + (size_t)(bn * 256) * K;

    const int nc = K >> 5;
    const int lrow = tid >> 2, lc = tid & 3;

    auto issue_stage = [&](int c) {
        if (c < nc) {
            const uint32_t sb = smem_u + (c % 3) * STAGE_BYTES;
            const int k0 = c * 32;
            #pragma unroll
            for (int i = 0; i < 2; i++) {
                const int row = lrow + i * 64;
                const uint32_t so = swz(row, lc);
                const size_t go = (size_t)row * K + k0 + lc * 8;
                cp_async16(sb + OFF_AHI + so, gAhi + go);
                cp_async16(sb + OFF_ALO + so, gAlo + go);
            }
            #pragma unroll
            for (int i = 0; i < 4; i++) {
                const int row = lrow + i * 64;
                const uint32_t so = swz(row, lc);
                const size_t go = (size_t)row * K + k0 + lc * 8;
                cp_async16(sb + OFF_BHI + so, gBhi + go);
                cp_async16(sb + OFF_BLO + so, gBlo + go);
            }
        }
        cp_commit();
    };

    float acc[4][8][4];
    #pragma unroll
    for (int i = 0; i < 4; i++)
        #pragma unroll
        for (int j = 0; j < 8; j++)
            #pragma unroll
            for (int t = 0; t < 4; t++) acc[i][j][t] = 0.f;

    issue_stage(0); issue_stage(1);

    const int lm_r = ((lane >> 3) & 1) * 8 + (lane & 7);
    const int lm_c = lane >> 4;

    for (int c = 0; c < nc; c++) {
        cp_wait<1>();
        __syncthreads();
        issue_stage(c + 2);
        const uint32_t sb = smem_u + (c % 3) * STAGE_BYTES;

        #pragma unroll
        for (int s = 0; s < 2; s++) {
            const int chunk = 2 * s + lm_c;
            uint32_t Bh[4][4], Bl[4][4];
            #pragma unroll
            for (int p = 0; p < 4; p++) {
                const int row = warp_n + p * 16 + lm_r;
                const uint32_t a = sb + OFF_BHI + swz(row, chunk);
                ldmatrix_x4(Bh[p], a);
                ldmatrix_x4(Bl[p], a + (OFF_BLO - OFF_BHI));
            }
            #pragma unroll
            for (int mi = 0; mi < 4; mi++) {
                const int row = warp_m + mi * 16 + lm_r;
                uint32_t Ah[4], Al[4];
                const uint32_t a = sb + OFF_AHI + swz(row, chunk);
                ldmatrix_x4(Ah, a);
                ldmatrix_x4(Al, a + (OFF_ALO - OFF_ALO) + swz(row, chunk) * 0); // placeholder no-op
                ldmatrix_x4(Al, sb + OFF_ALO + swz(row, chunk));
                #pragma unroll
                for (int ni = 0; ni < 8; ni++) {
                    const int p = ni >> 1, q = ni & 1;
                    mma16816(acc[mi][ni], Ah, Bh[p][q], Bh[p][2 + q]);
                    mma16816(acc[mi][ni], Ah, Bl[p][q], Bl[p][2 + q]);
                    mma16816(acc[mi][ni], Al, Bh[p][q], Bh[p][2 + q]);
                }
            }
        }
    }

    const int g = lane >> 2, tig = lane & 3;
    #pragma unroll
    for (int ni = 0; ni < 8; ni++) {
        const int n = bn * 256 + warp_n + ni * 8 + tig * 2;
        const float b0 = __ldg(bias + n), b1 = __ldg(bias + n + 1);
        #pragma unroll
        for (int mi = 0; mi < 4; mi++) {
            const int m0 = bm * 128 + warp_m + mi * 16 + g;
            #pragma unroll
            for (int half = 0; half < 2; half++) {
                const int m = m0 + half * 8;
                float v0 = acc[mi][ni][half * 2 + 0] + b0;
                float v1 = acc[mi][ni][half * 2 + 1] + b1;
                if (do_elu) {
                    v0 = (v0 > 0.f) ? (v0 + 1.f) : expf(v0);
                    v1 = (v1 > 0.f) ? (v1 + 1.f) : expf(v1);
                }
                *(float2*)(Cf + (size_t)m * N + n) = make_float2(v0, v1);
            }
        }
    }
}

// ======================= attention stage 1: partial KV over 4 L-slices =======================
__global__ void __launch_bounds__(256)
attn_kv_kernel(const float* __restrict__ Kf, const float* __restrict__ Vf,
               float* __restrict__ KVp, float* __restrict__ Ksp)
{
    const int bh = blockIdx.x;
    const int part = blockIdx.y;
    const int b = bh >> 4, h = bh & 15;
    __shared__ float Ks[64][68];
    __shared__ float Vs[64][68];
    const int tid = threadIdx.x;
    const int d0 = (tid >> 4) * 4, m0 = (tid & 15) * 4;

    float acc[4][4];
    #pragma unroll
    for (int i = 0; i < 4; i++)
        #pragma unroll
        for (int j = 0; j < 4; j++) acc[i][j] = 0.f;
    float ksacc = 0.f;

    const size_t base0 = ((size_t)b * LL) * EE + h * DD;
    const int s_begin = part * (LL / 4), s_end = s_begin + LL / 4;

    for (int s0 = s_begin; s0 < s_end; s0 += 64) {
        #pragma unroll
        for (int j = 0; j < 4; j++) {
            const int id = tid + j * 256;
            const int r = id >> 4, c4 = id & 15;
            const size_t ga = base0 + (size_t)(s0 + r) * EE + c4 * 4;
            float4 kk = *(const float4*)(Kf + ga);
            float4 vv = *(const float4*)(Vf + ga);
            Ks[r][c4*4+0]=kk.x; Ks[r][c4*4+1]=kk.y; Ks[r][c4*4+2]=kk.z; Ks[r][c4*4+3]=kk.w;
            Vs[r][c4*4+0]=vv.x; Vs[r][c4*4+1]=vv.y; Vs[r][c4*4+2]=vv.z; Vs[r][c4*4+3]=vv.w;
        }
        __syncthreads();

        if (tid < 64) {
            #pragma unroll 8
            for (int s = 0; s < 64; s++) ksacc += Ks[s][tid];
        }
        #pragma unroll 4
        for (int s = 0; s < 64; s++) {
            float4 kd = *(const float4*)&Ks[s][d0];
            float4 vm = *(const float4*)&Vs[s][m0];
            float ka[4] = {kd.x, kd.y, kd.z, kd.w};
            float va[4] = {vm.x, vm.y, vm.z, vm.w};
            #pragma unroll
            for (int i = 0; i < 4; i++)
                #pragma unroll
                for (int j = 0; j < 4; j++)
                    acc[i][j] += ka[i] * va[j];
        }
        __syncthreads();
    }

    float* kvdst = KVp + ((size_t)(part * (BB*HH) + bh) * DD) * DD;
    #pragma unroll
    for (int i = 0; i < 4; i++)
        *(float4*)(kvdst + (size_t)(d0 + i) * DD + m0) =
            make_float4(acc[i][0], acc[i][1], acc[i][2], acc[i][3]);
    if (tid < 64) Ksp[(part * (BB*HH) + bh) * DD + tid] = ksacc;
}

// ======================= attention stage 2 (sums partials; writes bf16 hi/lo) =======================
__global__ void __launch_bounds__(256)
attn_out_kernel(const float* __restrict__ Qf, const float* __restrict__ KVp,
                const float* __restrict__ Ksp,
                __nv_bfloat16* __restrict__ Ohi, __nv_bfloat16* __restrict__ Olo)
{
    const int bh = blockIdx.y;
    const int b = bh >> 4, h = bh & 15;
    const int tid = threadIdx.x;
    __shared__ float KVs[64][64];
    __shared__ float ks[64];

    #pragma unroll
    for (int j = 0; j < 4; j++) {
        const int id = tid + j * 256;
        float4 a = make_float4(0.f, 0.f, 0.f, 0.f);
        #pragma unroll
        for (int part = 0; part < 4; part++) {
            float4 p = ((const float4*)(KVp + (size_t)(part * (BB*HH) + bh) * DD * DD))[id];
            a.x += p.x; a.y += p.y; a.z += p.z; a.w += p.w;
        }
        ((float4*)&KVs[0][0])[id] = a;
    }
    if (tid < 16) {
        float4 a = make_float4(0.f, 0.f, 0.f, 0.f);
        #pragma unroll
        for (int part = 0; part < 4; part++) {
            float4 p = ((const float4*)(Ksp + (part * (BB*HH) + bh) * DD))[tid];
            a.x += p.x; a.y += p.y; a.z += p.z; a.w += p.w;
        }
        ((float4*)ks)[tid] = a;
    }
    __syncthreads();

    const int row = b * LL + blockIdx.x * 256 + tid;
    const float4* qrow = (const float4*)(Qf + (size_t)row * EE + h * DD);

    float z = 0.f;
    #pragma unroll
    for (int d4 = 0; d4 < 16; d4++) {
        float4 qv = qrow[d4];
        float4 kv = ((const float4*)ks)[d4];
        z += qv.x*kv.x + qv.y*kv.y + qv.z*kv.z + qv.w*kv.w;
    }
    const float zi = 1.0f / (z + ATTN_EPS);

    float acc[64];
    #pragma unroll
    for (int j = 0; j < 64; j++) acc[j] = 0.f;

    for (int d4 = 0; d4 < 16; d4++) {
        float4 qv = qrow[d4];
        float qs[4] = {qv.x, qv.y, qv.z, qv.w};
        #pragma unroll
        for (int dd = 0; dd < 4; dd++) {
            const float qd = qs[dd];
            const float4* kvr = (const float4*)&KVs[d4 * 4 + dd][0];
            #pragma unroll
            for (int j4 = 0; j4 < 16; j4++) {
                float4 kv = kvr[j4];
                acc[j4*4+0] += qd * kv.x;
                acc[j4*4+1] += qd * kv.y;
                acc[j4*4+2] += qd * kv.z;
                acc[j4*4+3] += qd * kv.w;
            }
        }
    }

    __nv_bfloat16* hp = Ohi + (size_t)row * EE + h * DD;
    __nv_bfloat16* lp = Olo + (size_t)row * EE + h * DD;
    #pragma unroll
    for (int j2 = 0; j2 < 32; j2++) {
        float a0 = acc[j2*2]   * zi;
        float a1 = acc[j2*2+1] * zi;
        __nv_bfloat16 h0 = __float2bfloat16(a0);
        __nv_bfloat16 h1 = __float2bfloat16(a1);
        ((__nv_bfloat162*)hp)[j2] = __halves2bfloat162(h0, h1);
        ((__nv_bfloat162*)lp)[j2] = __halves2bfloat162(
            __float2bfloat16(a0 - __bfloat162float(h0)),
            __float2bfloat16(a1 - __bfloat162float(h1)));
    }
}

// ======================= host launcher =======================
extern "C" void kernel_launch(void* const* d_in, const int* in_sizes, int n_in,
                              void* d_out, int out_size)
{
    const float* x     = (const float*)d_in[0];
    const float* ln1_g = (const float*)d_in[1];
    const float* ln1_b = (const float*)d_in[2];
    const float* ln2_g = (const float*)d_in[3];
    const float* ln2_b = (const float*)d_in[4];
    const float* Wq = (const float*)d_in[5];  const float* bq = (const float*)d_in[6];
    const float* Wk = (const float*)d_in[7];  const float* bk = (const float*)d_in[8];
    const float* Wv = (const float*)d_in[9];  const float* bv = (const float*)d_in[10];
    const float* Wo = (const float*)d_in[11]; const float* bo = (const float*)d_in[12];
    const float* W1 = (const float*)d_in[13]; const float* b1 = (const float*)d_in[14];
    const float* W2 = (const float*)d_in[15]; const float* b2 = (const float*)d_in[16];
    float* out = (float*)d_out;

    #define SYM(T, name, sym) T* name; { void* p; cudaGetSymbolAddress(&p, sym); name = (T*)p; }
    SYM(__nv_bfloat16, hhi, g_hhi)  SYM(__nv_bfloat16, hlo, g_hlo)
    SYM(__nv_bfloat16, aohi, g_aohi) SYM(__nv_bfloat16, aolo, g_aolo)
    SYM(__nv_bfloat16, f1hi, g_f1hi) SYM(__nv_bfloat16, f1lo, g_f1lo)
    SYM(float, q, g_q)  SYM(float, k, g_k)  SYM(float, v, g_v)  SYM(float, x2, g_x2)
    SYM(__nv_bfloat16, wqhi, g_wqhi) SYM(__nv_bfloat16, wqlo, g_wqlo)
    SYM(__nv_bfloat16, wkhi, g_wkhi) SYM(__nv_bfloat16, wklo, g_wklo)
    SYM(__nv_bfloat16, wvhi, g_wvhi) SYM(__nv_bfloat16, wvlo, g_wvlo)
    SYM(__nv_bfloat16, wohi, g_wohi) SYM(__nv_bfloat16, wolo, g_wolo)
    SYM(__nv_bfloat16, w1hi, g_w1hi) SYM(__nv_bfloat16, w1lo, g_w1lo)
    SYM(__nv_bfloat16, w2hi, g_w2hi) SYM(__nv_bfloat16, w2lo, g_w2lo)
    SYM(float, kvp, g_kvp) SYM(float, ksp, g_ksp)
    #undef SYM

    cudaFuncSetAttribute(gemm_qkv,      cudaFuncAttributeMaxDynamicSharedMemorySize, GEMM_SMEM);
    cudaFuncSetAttribute(gemm3bf<3,0>, cudaFuncAttributeMaxDynamicSharedMemorySize, GEMM_SMEM);
    cudaFuncSetAttribute(gemm3bf<2,1>, cudaFuncAttributeMaxDynamicSharedMemorySize, GEMM_SMEM);

    // 1. fused weight conversion (single launch)
    const int total4 = 4 * NE4 + 2 * NF4;
    cvt_all_kernel<<<total4 / 256, 256>>>(Wq, Wk, Wv, Wo, W1, W2,
        wqhi, wqlo, wkhi, wklo, wvhi, wvlo, wohi, wolo, w1hi, w1lo, w2hi, w2lo);
    // 2. LN1 -> h hi/lo
    ln_hilo_kernel<<<MM, 256>>>(x, ln1_g, ln1_b, hhi, hlo);
    // 3. fused QKV projection (elu+1 on q,k)
    gemm_qkv<<<dim3(12, MM / 128), 256, GEMM_SMEM>>>(hhi, hlo,
        wqhi, wqlo, wkhi, wklo, wvhi, wvlo, bq, bk, bv, q, k, v);
    // 4. linear attention
    attn_kv_kernel<<<dim3(BB * HH, 4), 256>>>(k, v, kvp, ksp);
    attn_out_kernel<<<dim3(LL / 256, BB * HH), 256>>>(q, kvp, ksp, aohi, aolo);
    // 5. Wo projection + residual -> x2
    gemm3bf<3,0><<<dim3(EE / 256, MM / 128), 256, GEMM_SMEM>>>(aohi, aolo, wohi, wolo,
        bo, x, x2, nullptr, nullptr, MM, EE, EE);
    // 6. LN2 -> h hi/lo (reuse)
    ln_hilo_kernel<<<MM, 256>>>(x2, ln2_g, ln2_b, hhi, hlo);
    // 7. FFN
    gemm3bf<2,1><<<dim3(FF / 256, MM / 128), 256, GEMM_SMEM>>>(hhi, hlo, w1hi, w1lo,
        b1, nullptr, nullptr, f1hi, f1lo, MM, FF, EE);
    gemm3bf<3,0><<<dim3(EE / 256, MM / 128), 256, GEMM_SMEM>>>(f1hi, f1lo, w2hi, w2lo,
        b2, x2, out, nullptr, nullptr, MM, EE, FF);
}

// round 5
// speedup vs baseline: 1.1649x; 1.1649x over previous
#include <cuda_runtime.h>
#include <cuda_bf16.h>
#include <math.h>
#include <stdint.h>

// Problem dims (fixed)
#define BB 8
#define LL 2048
#define EE 1024
#define HH 16
#define DD 64
#define MM (BB*LL)      // 16384 rows
#define FF (4*EE)       // 4096 ffn dim

#define LN_EPS 1e-5f
#define ATTN_EPS 1e-6f

// ======================= helpers =======================
__device__ __forceinline__ uint32_t smem_to_u32(const void* smem_ptr) {
    uint32_t addr;
    asm("{ .reg .u64 tmp; cvta.to.shared.u64 tmp, %1; cvt.u32.u64 %0, tmp; }"
        : "=r"(addr) : "l"(smem_ptr));
    return addr;
}

__device__ __forceinline__ void cp_async16(uint32_t saddr, const void* gptr) {
    asm volatile("cp.async.cg.shared.global [%0], [%1], 16;" :: "r"(saddr), "l"(gptr));
}
__device__ __forceinline__ void cp_commit() {
    asm volatile("cp.async.commit_group;");
}
template<int N>
__device__ __forceinline__ void cp_wait() {
    asm volatile("cp.async.wait_group %0;" :: "n"(N));
}

__device__ __forceinline__ void ldmatrix_x4(uint32_t* r, uint32_t addr) {
    asm volatile("ldmatrix.sync.aligned.m8n8.x4.shared.b16 {%0,%1,%2,%3}, [%4];"
                 : "=r"(r[0]), "=r"(r[1]), "=r"(r[2]), "=r"(r[3]) : "r"(addr));
}

__device__ __forceinline__ void mma16816(float* c, const uint32_t* a, uint32_t b0, uint32_t b1) {
    asm volatile(
        "mma.sync.aligned.m16n8k16.row.col.f32.bf16.bf16.f32 "
        "{%0,%1,%2,%3}, {%4,%5,%6,%7}, {%8,%9}, {%0,%1,%2,%3};"
        : "+f"(c[0]), "+f"(c[1]), "+f"(c[2]), "+f"(c[3])
        : "r"(a[0]), "r"(a[1]), "r"(a[2]), "r"(a[3]), "r"(b0), "r"(b1));
}

// ======================= scratch (device globals) =======================
__device__ __align__(256) __nv_bfloat16 g_hhi [(size_t)MM * EE];
__device__ __align__(256) __nv_bfloat16 g_hlo [(size_t)MM * EE];
__device__ __align__(256) __nv_bfloat16 g_aohi[(size_t)MM * EE];
__device__ __align__(256) __nv_bfloat16 g_aolo[(size_t)MM * EE];
__device__ __align__(256) __nv_bfloat16 g_f1hi[(size_t)MM * FF];
__device__ __align__(256) __nv_bfloat16 g_f1lo[(size_t)MM * FF];
__device__ __align__(256) float g_q [(size_t)MM * EE];
__device__ __align__(256) float g_k [(size_t)MM * EE];
__device__ __align__(256) float g_v [(size_t)MM * EE];
__device__ __align__(256) float g_x2[(size_t)MM * EE];
__device__ __align__(256) __nv_bfloat16 g_wqhi[(size_t)EE*EE], g_wqlo[(size_t)EE*EE];
__device__ __align__(256) __nv_bfloat16 g_wkhi[(size_t)EE*EE], g_wklo[(size_t)EE*EE];
__device__ __align__(256) __nv_bfloat16 g_wvhi[(size_t)EE*EE], g_wvlo[(size_t)EE*EE];
__device__ __align__(256) __nv_bfloat16 g_wohi[(size_t)EE*EE], g_wolo[(size_t)EE*EE];
__device__ __align__(256) __nv_bfloat16 g_w1hi[(size_t)FF*EE], g_w1lo[(size_t)FF*EE];
__device__ __align__(256) __nv_bfloat16 g_w2hi[(size_t)EE*FF], g_w2lo[(size_t)EE*FF];
__device__ __align__(256) float g_kvp[4 * BB * HH * DD * DD]; // partial KV
__device__ __align__(256) float g_ksp[4 * BB * HH * DD];      // partial Ksum

// ======================= fused fp32 -> bf16 hi/lo weight conversion =======================
#define NE4 (EE*EE/4)
#define NF4 (EE*FF/4)
__global__ void cvt_all_kernel(
    const float* __restrict__ Wq, const float* __restrict__ Wk,
    const float* __restrict__ Wv, const float* __restrict__ Wo,
    const float* __restrict__ W1, const float* __restrict__ W2,
    __nv_bfloat16* __restrict__ qh, __nv_bfloat16* __restrict__ ql,
    __nv_bfloat16* __restrict__ kh, __nv_bfloat16* __restrict__ kl,
    __nv_bfloat16* __restrict__ vh, __nv_bfloat16* __restrict__ vl,
    __nv_bfloat16* __restrict__ oh, __nv_bfloat16* __restrict__ ol,
    __nv_bfloat16* __restrict__ f1h, __nv_bfloat16* __restrict__ f1l,
    __nv_bfloat16* __restrict__ f2h, __nv_bfloat16* __restrict__ f2l)
{
    int i = blockIdx.x * 256 + threadIdx.x;
    const float* s; __nv_bfloat16 *hi, *lo; int off;
    if (i < 4 * NE4) {
        int w = i / NE4; off = i - w * NE4;
        s  = (w == 0) ? Wq : (w == 1) ? Wk : (w == 2) ? Wv : Wo;
        hi = (w == 0) ? qh : (w == 1) ? kh : (w == 2) ? vh : oh;
        lo = (w == 0) ? ql : (w == 1) ? kl : (w == 2) ? vl : ol;
    } else {
        int j = i - 4 * NE4;
        int w = j / NF4; off = j - w * NF4;
        s  = (w == 0) ? W1 : W2;
        hi = (w == 0) ? f1h : f2h;
        lo = (w == 0) ? f1l : f2l;
    }
    float4 v = ((const float4*)s)[off];
    __nv_bfloat16 h0 = __float2bfloat16(v.x), h1 = __float2bfloat16(v.y);
    __nv_bfloat16 h2 = __float2bfloat16(v.z), h3 = __float2bfloat16(v.w);
    ((__nv_bfloat162*)hi)[2*off]   = __halves2bfloat162(h0, h1);
    ((__nv_bfloat162*)hi)[2*off+1] = __halves2bfloat162(h2, h3);
    ((__nv_bfloat162*)lo)[2*off]   = __halves2bfloat162(
        __float2bfloat16(v.x - __bfloat162float(h0)),
        __float2bfloat16(v.y - __bfloat162float(h1)));
    ((__nv_bfloat162*)lo)[2*off+1] = __halves2bfloat162(
        __float2bfloat16(v.z - __bfloat162float(h2)),
        __float2bfloat16(v.w - __bfloat162float(h3)));
}

// ======================= LayerNorm (writes bf16 hi/lo) =======================
__global__ void ln_hilo_kernel(const float* __restrict__ x,
                               const float* __restrict__ g,
                               const float* __restrict__ b,
                               __nv_bfloat16* __restrict__ yhi,
                               __nv_bfloat16* __restrict__ ylo)
{
    const int row = blockIdx.x;
    const int tid = threadIdx.x;
    const float4* xr = (const float4*)(x + (size_t)row * EE);
    float4 v = xr[tid];
    float s  = v.x + v.y + v.z + v.w;
    float sq = v.x*v.x + v.y*v.y + v.z*v.z + v.w*v.w;

    #pragma unroll
    for (int off = 16; off > 0; off >>= 1) {
        s  += __shfl_xor_sync(0xffffffffu, s,  off);
        sq += __shfl_xor_sync(0xffffffffu, sq, off);
    }
    __shared__ float ws[8], wsq[8];
    __shared__ float s_mean, s_rstd;
    const int wid = tid >> 5, lane = tid & 31;
    if (lane == 0) { ws[wid] = s; wsq[wid] = sq; }
    __syncthreads();
    if (tid == 0) {
        float ts = 0.f, tsq = 0.f;
        #pragma unroll
        for (int i = 0; i < 8; i++) { ts += ws[i]; tsq += wsq[i]; }
        float mean = ts * (1.0f / EE);
        float var  = tsq * (1.0f / EE) - mean * mean;
        s_mean = mean;
        s_rstd = rsqrtf(var + LN_EPS);
    }
    __syncthreads();
    const float mean = s_mean, rstd = s_rstd;
    float4 gg = ((const float4*)g)[tid];
    float4 bb = ((const float4*)b)[tid];
    float o0 = (v.x - mean) * rstd * gg.x + bb.x;
    float o1 = (v.y - mean) * rstd * gg.y + bb.y;
    float o2 = (v.z - mean) * rstd * gg.z + bb.z;
    float o3 = (v.w - mean) * rstd * gg.w + bb.w;
    __nv_bfloat16 h0 = __float2bfloat16(o0), h1 = __float2bfloat16(o1);
    __nv_bfloat16 h2 = __float2bfloat16(o2), h3 = __float2bfloat16(o3);
    __nv_bfloat162* hp = (__nv_bfloat162*)(yhi + (size_t)row * EE + tid * 4);
    __nv_bfloat162* lp = (__nv_bfloat162*)(ylo + (size_t)row * EE + tid * 4);
    hp[0] = __halves2bfloat162(h0, h1);
    hp[1] = __halves2bfloat162(h2, h3);
    lp[0] = __halves2bfloat162(__float2bfloat16(o0 - __bfloat162float(h0)),
                               __float2bfloat16(o1 - __bfloat162float(h1)));
    lp[1] = __halves2bfloat162(__float2bfloat16(o2 - __bfloat162float(h2)),
                               __float2bfloat16(o3 - __bfloat162float(h3)));
}

// ======================= mma.sync 3xBF16 GEMM (R3 shape + single-sync loop) =======================
// CTA 128x128, 8 warps (2x4), warp tile 64x32, K-chunk 32, 3-stage cp.async ring.
#define STAGE_BYTES 32768
#define OFF_AHI 0
#define OFF_ALO 8192
#define OFF_BHI 16384
#define OFF_BLO 24576
#define GEMM_SMEM (3*STAGE_BYTES)

__device__ __forceinline__ uint32_t swz(int row, int c) {
    return (uint32_t)(row * 64 + ((c ^ ((row >> 1) & 3)) << 4));
}

// Mainloop body shared by both GEMM kernels.
// Defines acc and runs the full K loop. Requires: smem_u, gAhi,gAlo,gBhi,gBlo, K, tid, lane,
// warp_m, warp_n in scope.
#define GEMM_MAINLOOP(ACC)                                                              \
    const int nc = K >> 5;                                                              \
    const int lrow = tid >> 2, lc = tid & 3;                                            \
    auto issue_stage = [&](int c) {                                                     \
        if (c < nc) {                                                                   \
            const uint32_t sb = smem_u + (c % 3) * STAGE_BYTES;                         \
            const int k0 = c * 32;                                                      \
            _Pragma("unroll")                                                           \
            for (int i = 0; i < 2; i++) {                                               \
                const int row = lrow + i * 64;                                          \
                const uint32_t so = swz(row, lc);                                       \
                const size_t go = (size_t)row * K + k0 + lc * 8;                        \
                cp_async16(sb + OFF_AHI + so, gAhi + go);                               \
                cp_async16(sb + OFF_ALO + so, gAlo + go);                               \
                cp_async16(sb + OFF_BHI + so, gBhi + go);                               \
                cp_async16(sb + OFF_BLO + so, gBlo + go);                               \
            }                                                                           \
        }                                                                               \
        cp_commit();                                                                    \
    };                                                                                  \
    issue_stage(0); issue_stage(1);                                                     \
    const int lm_r = ((lane >> 3) & 1) * 8 + (lane & 7);                                \
    const int lm_c = lane >> 4;                                                         \
    for (int c = 0; c < nc; c++) {                                                      \
        cp_wait<1>();                                                                   \
        __syncthreads();                                                                \
        issue_stage(c + 2);                                                             \
        const uint32_t sb = smem_u + (c % 3) * STAGE_BYTES;                             \
        _Pragma("unroll")                                                               \
        for (int s = 0; s < 2; s++) {                                                   \
            const int chunk = 2 * s + lm_c;                                             \
            uint32_t Bh[2][4], Bl[2][4];                                                \
            _Pragma("unroll")                                                           \
            for (int p = 0; p < 2; p++) {                                               \
                const int row = warp_n + p * 16 + lm_r;                                 \
                const uint32_t a = sb + OFF_BHI + swz(row, chunk);                      \
                ldmatrix_x4(Bh[p], a);                                                  \
                ldmatrix_x4(Bl[p], a + (OFF_BLO - OFF_BHI));                            \
            }                                                                           \
            _Pragma("unroll")                                                           \
            for (int mi = 0; mi < 4; mi++) {                                            \
                const int row = warp_m + mi * 16 + lm_r;                                \
                uint32_t Ah[4], Al[4];                                                  \
                const uint32_t a = sb + OFF_AHI + swz(row, chunk);                      \
                ldmatrix_x4(Ah, a);                                                     \
                ldmatrix_x4(Al, a + (OFF_ALO - OFF_AHI));                               \
                _Pragma("unroll")                                                       \
                for (int ni = 0; ni < 4; ni++) {                                        \
                    const int p = ni >> 1, q = ni & 1;                                  \
                    mma16816(ACC[mi][ni], Ah, Bh[p][q], Bh[p][2 + q]);                  \
                    mma16816(ACC[mi][ni], Ah, Bl[p][q], Bl[p][2 + q]);                  \
                    mma16816(ACC[mi][ni], Al, Bh[p][q], Bh[p][2 + q]);                  \
                }                                                                       \
            }                                                                           \
        }                                                                               \
    }

template<int EPI, int OUT>   // EPI: 0 none, 2 relu, 3 +residual ; OUT: 0 fp32, 1 bf16 hi/lo
__global__ void __launch_bounds__(256, 2)
gemm3bf(const __nv_bfloat16* __restrict__ Ahi, const __nv_bfloat16* __restrict__ Alo,
        const __nv_bfloat16* __restrict__ Bhi, const __nv_bfloat16* __restrict__ Blo,
        const float* __restrict__ bias, const float* __restrict__ Rres,
        float* __restrict__ Cf, __nv_bfloat16* __restrict__ Chi,
        __nv_bfloat16* __restrict__ Clo,
        int M, int N, int K)
{
    extern __shared__ __align__(128) char smem[];
    const uint32_t smem_u = smem_to_u32(smem);

    const int tid = threadIdx.x;
    const int wid = tid >> 5, lane = tid & 31;
    const int bm = blockIdx.y, bn = blockIdx.x;
    const int warp_m = (wid >> 2) * 64;
    const int warp_n = (wid & 3) * 32;

    const __nv_bfloat16* gAhi = Ahi + (size_t)(bm * 128) * K;
    const __nv_bfloat16* gAlo = Alo + (size_t)(bm * 128) * K;
    const __nv_bfloat16* gBhi = Bhi + (size_t)(bn * 128) * K;
    const __nv_bfloat16* gBlo = Blo + (size_t)(bn * 128) * K;

    float acc[4][4][4];
    #pragma unroll
    for (int i = 0; i < 4; i++)
        #pragma unroll
        for (int j = 0; j < 4; j++)
            #pragma unroll
            for (int t = 0; t < 4; t++) acc[i][j][t] = 0.f;

    GEMM_MAINLOOP(acc)

    // ---------------- epilogue ----------------
    const int g = lane >> 2, tig = lane & 3;
    #pragma unroll
    for (int ni = 0; ni < 4; ni++) {
        const int n = bn * 128 + warp_n + ni * 8 + tig * 2;
        const float b0 = __ldg(bias + n), b1 = __ldg(bias + n + 1);
        #pragma unroll
        for (int mi = 0; mi < 4; mi++) {
            const int m0 = bm * 128 + warp_m + mi * 16 + g;
            #pragma unroll
            for (int half = 0; half < 2; half++) {
                const int m = m0 + half * 8;
                float v0 = acc[mi][ni][half * 2 + 0] + b0;
                float v1 = acc[mi][ni][half * 2 + 1] + b1;
                if (EPI == 2) { v0 = fmaxf(v0, 0.f); v1 = fmaxf(v1, 0.f); }
                else if (EPI == 3) {
                    const float2 rv = *(const float2*)(Rres + (size_t)m * N + n);
                    v0 += rv.x; v1 += rv.y;
                }
                if (OUT == 0) {
                    *(float2*)(Cf + (size_t)m * N + n) = make_float2(v0, v1);
                } else {
                    __nv_bfloat16 h0 = __float2bfloat16(v0);
                    __nv_bfloat16 h1 = __float2bfloat16(v1);
                    *(__nv_bfloat162*)(Chi + (size_t)m * N + n) = __halves2bfloat162(h0, h1);
                    *(__nv_bfloat162*)(Clo + (size_t)m * N + n) = __halves2bfloat162(
                        __float2bfloat16(v0 - __bfloat162float(h0)),
                        __float2bfloat16(v1 - __bfloat162float(h1)));
                }
            }
        }
    }
}

// ---- fused QKV GEMM: bnL in [0,24); w = bnL>>3 selects Wq/Wk/Wv; elu+1 on q,k ----
__global__ void __launch_bounds__(256, 2)
gemm_qkv(const __nv_bfloat16* __restrict__ Ahi, const __nv_bfloat16* __restrict__ Alo,
         const __nv_bfloat16* __restrict__ wqh, const __nv_bfloat16* __restrict__ wql,
         const __nv_bfloat16* __restrict__ wkh, const __nv_bfloat16* __restrict__ wkl,
         const __nv_bfloat16* __restrict__ wvh, const __nv_bfloat16* __restrict__ wvl,
         const float* __restrict__ bqp, const float* __restrict__ bkp,
         const float* __restrict__ bvp,
         float* __restrict__ oq, float* __restrict__ ok, float* __restrict__ ov)
{
    extern __shared__ __align__(128) char smem[];
    const uint32_t smem_u = smem_to_u32(smem);
    const int K = EE, N = EE;

    const int tid = threadIdx.x;
    const int wid = tid >> 5, lane = tid & 31;
    const int bm = blockIdx.y, bnL = blockIdx.x;
    const int w = bnL >> 3, bn = bnL & 7;
    const int warp_m = (wid >> 2) * 64;
    const int warp_n = (wid & 3) * 32;

    const __nv_bfloat16* Bhi = (w == 0) ? wqh : (w == 1) ? wkh : wvh;
    const __nv_bfloat16* Blo = (w == 0) ? wql : (w == 1) ? wkl : wvl;
    const float* bias = (w == 0) ? bqp : (w == 1) ? bkp : bvp;
    float* Cf = (w == 0) ? oq : (w == 1) ? ok : ov;
    const bool do_elu = (w < 2);

    const __nv_bfloat16* gAhi = Ahi + (size_t)(bm * 128) * K;
    const __nv_bfloat16* gAlo = Alo + (size_t)(bm * 128) * K;
    const __nv_bfloat16* gBhi = Bhi + (size_t)(bn * 128) * K;
    const __nv_bfloat16* gBlo = Blo + (size_t)(bn * 128) * K;

    float acc[4][4][4];
    #pragma unroll
    for (int i = 0; i < 4; i++)
        #pragma unroll
        for (int j = 0; j < 4; j++)
            #pragma unroll
            for (int t = 0; t < 4; t++) acc[i][j][t] = 0.f;

    GEMM_MAINLOOP(acc)

    const int g = lane >> 2, tig = lane & 3;
    #pragma unroll
    for (int ni = 0; ni < 4; ni++) {
        const int n = bn * 128 + warp_n + ni * 8 + tig * 2;
        const float b0 = __ldg(bias + n), b1 = __ldg(bias + n + 1);
        #pragma unroll
        for (int mi = 0; mi < 4; mi++) {
            const int m0 = bm * 128 + warp_m + mi * 16 + g;
            #pragma unroll
            for (int half = 0; half < 2; half++) {
                const int m = m0 + half * 8;
                float v0 = acc[mi][ni][half * 2 + 0] + b0;
                float v1 = acc[mi][ni][half * 2 + 1] + b1;
                if (do_elu) {
                    v0 = (v0 > 0.f) ? (v0 + 1.f) : expf(v0);
                    v1 = (v1 > 0.f) ? (v1 + 1.f) : expf(v1);
                }
                *(float2*)(Cf + (size_t)m * N + n) = make_float2(v0, v1);
            }
        }
    }
}

// ======================= attention stage 1: partial KV over 4 L-slices =======================
__global__ void __launch_bounds__(256)
attn_kv_kernel(const float* __restrict__ Kf, const float* __restrict__ Vf,
               float* __restrict__ KVp, float* __restrict__ Ksp)
{
    const int bh = blockIdx.x;
    const int part = blockIdx.y;
    const int b = bh >> 4, h = bh & 15;
    __shared__ float Ks[64][68];
    __shared__ float Vs[64][68];
    const int tid = threadIdx.x;
    const int d0 = (tid >> 4) * 4, m0 = (tid & 15) * 4;

    float acc[4][4];
    #pragma unroll
    for (int i = 0; i < 4; i++)
        #pragma unroll
        for (int j = 0; j < 4; j++) acc[i][j] = 0.f;
    float ksacc = 0.f;

    const size_t base0 = ((size_t)b * LL) * EE + h * DD;
    const int s_begin = part * (LL / 4), s_end = s_begin + LL / 4;

    for (int s0 = s_begin; s0 < s_end; s0 += 64) {
        #pragma unroll
        for (int j = 0; j < 4; j++) {
            const int id = tid + j * 256;
            const int r = id >> 4, c4 = id & 15;
            const size_t ga = base0 + (size_t)(s0 + r) * EE + c4 * 4;
            float4 kk = *(const float4*)(Kf + ga);
            float4 vv = *(const float4*)(Vf + ga);
            Ks[r][c4*4+0]=kk.x; Ks[r][c4*4+1]=kk.y; Ks[r][c4*4+2]=kk.z; Ks[r][c4*4+3]=kk.w;
            Vs[r][c4*4+0]=vv.x; Vs[r][c4*4+1]=vv.y; Vs[r][c4*4+2]=vv.z; Vs[r][c4*4+3]=vv.w;
        }
        __syncthreads();

        if (tid < 64) {
            #pragma unroll 8
            for (int s = 0; s < 64; s++) ksacc += Ks[s][tid];
        }
        #pragma unroll 4
        for (int s = 0; s < 64; s++) {
            float4 kd = *(const float4*)&Ks[s][d0];
            float4 vm = *(const float4*)&Vs[s][m0];
            float ka[4] = {kd.x, kd.y, kd.z, kd.w};
            float va[4] = {vm.x, vm.y, vm.z, vm.w};
            #pragma unroll
            for (int i = 0; i < 4; i++)
                #pragma unroll
                for (int j = 0; j < 4; j++)
                    acc[i][j] += ka[i] * va[j];
        }
        __syncthreads();
    }

    float* kvdst = KVp + ((size_t)(part * (BB*HH) + bh) * DD) * DD;
    #pragma unroll
    for (int i = 0; i < 4; i++)
        *(float4*)(kvdst + (size_t)(d0 + i) * DD + m0) =
            make_float4(acc[i][0], acc[i][1], acc[i][2], acc[i][3]);
    if (tid < 64) Ksp[(part * (BB*HH) + bh) * DD + tid] = ksacc;
}

// ======================= attention stage 2 (sums partials; writes bf16 hi/lo) =======================
__global__ void __launch_bounds__(256)
attn_out_kernel(const float* __restrict__ Qf, const float* __restrict__ KVp,
                const float* __restrict__ Ksp,
                __nv_bfloat16* __restrict__ Ohi, __nv_bfloat16* __restrict__ Olo)
{
    const int bh = blockIdx.y;
    const int b = bh >> 4, h = bh & 15;
    const int tid = threadIdx.x;
    __shared__ float KVs[64][64];
    __shared__ float ks[64];

    #pragma unroll
    for (int j = 0; j < 4; j++) {
        const int id = tid + j * 256;
        float4 a = make_float4(0.f, 0.f, 0.f, 0.f);
        #pragma unroll
        for (int part = 0; part < 4; part++) {
            float4 p = ((const float4*)(KVp + (size_t)(part * (BB*HH) + bh) * DD * DD))[id];
            a.x += p.x; a.y += p.y; a.z += p.z; a.w += p.w;
        }
        ((float4*)&KVs[0][0])[id] = a;
    }
    if (tid < 16) {
        float4 a = make_float4(0.f, 0.f, 0.f, 0.f);
        #pragma unroll
        for (int part = 0; part < 4; part++) {
            float4 p = ((const float4*)(Ksp + (part * (BB*HH) + bh) * DD))[tid];
            a.x += p.x; a.y += p.y; a.z += p.z; a.w += p.w;
        }
        ((float4*)ks)[tid] = a;
    }
    __syncthreads();

    const int row = b * LL + blockIdx.x * 256 + tid;
    const float4* qrow = (const float4*)(Qf + (size_t)row * EE + h * DD);

    float z = 0.f;
    #pragma unroll
    for (int d4 = 0; d4 < 16; d4++) {
        float4 qv = qrow[d4];
        float4 kv = ((const float4*)ks)[d4];
        z += qv.x*kv.x + qv.y*kv.y + qv.z*kv.z + qv.w*kv.w;
    }
    const float zi = 1.0f / (z + ATTN_EPS);

    float acc[64];
    #pragma unroll
    for (int j = 0; j < 64; j++) acc[j] = 0.f;

    for (int d4 = 0; d4 < 16; d4++) {
        float4 qv = qrow[d4];
        float qs[4] = {qv.x, qv.y, qv.z, qv.w};
        #pragma unroll
        for (int dd = 0; dd < 4; dd++) {
            const float qd = qs[dd];
            const float4* kvr = (const float4*)&KVs[d4 * 4 + dd][0];
            #pragma unroll
            for (int j4 = 0; j4 < 16; j4++) {
                float4 kv = kvr[j4];
                acc[j4*4+0] += qd * kv.x;
                acc[j4*4+1] += qd * kv.y;
                acc[j4*4+2] += qd * kv.z;
                acc[j4*4+3] += qd * kv.w;
            }
        }
    }

    __nv_bfloat16* hp = Ohi + (size_t)row * EE + h * DD;
    __nv_bfloat16* lp = Olo + (size_t)row * EE + h * DD;
    #pragma unroll
    for (int j2 = 0; j2 < 32; j2++) {
        float a0 = acc[j2*2]   * zi;
        float a1 = acc[j2*2+1] * zi;
        __nv_bfloat16 h0 = __float2bfloat16(a0);
        __nv_bfloat16 h1 = __float2bfloat16(a1);
        ((__nv_bfloat162*)hp)[j2] = __halves2bfloat162(h0, h1);
        ((__nv_bfloat162*)lp)[j2] = __halves2bfloat162(
            __float2bfloat16(a0 - __bfloat162float(h0)),
            __float2bfloat16(a1 - __bfloat162float(h1)));
    }
}

// ======================= host launcher =======================
extern "C" void kernel_launch(void* const* d_in, const int* in_sizes, int n_in,
                              void* d_out, int out_size)
{
    const float* x     = (const float*)d_in[0];
    const float* ln1_g = (const float*)d_in[1];
    const float* ln1_b = (const float*)d_in[2];
    const float* ln2_g = (const float*)d_in[3];
    const float* ln2_b = (const float*)d_in[4];
    const float* Wq = (const float*)d_in[5];  const float* bq = (const float*)d_in[6];
    const float* Wk = (const float*)d_in[7];  const float* bk = (const float*)d_in[8];
    const float* Wv = (const float*)d_in[9];  const float* bv = (const float*)d_in[10];
    const float* Wo = (const float*)d_in[11]; const float* bo = (const float*)d_in[12];
    const float* W1 = (const float*)d_in[13]; const float* b1 = (const float*)d_in[14];
    const float* W2 = (const float*)d_in[15]; const float* b2 = (const float*)d_in[16];
    float* out = (float*)d_out;

    #define SYM(T, name, sym) T* name; { void* p; cudaGetSymbolAddress(&p, sym); name = (T*)p; }
    SYM(__nv_bfloat16, hhi, g_hhi)  SYM(__nv_bfloat16, hlo, g_hlo)
    SYM(__nv_bfloat16, aohi, g_aohi) SYM(__nv_bfloat16, aolo, g_aolo)
    SYM(__nv_bfloat16, f1hi, g_f1hi) SYM(__nv_bfloat16, f1lo, g_f1lo)
    SYM(float, q, g_q)  SYM(float, k, g_k)  SYM(float, v, g_v)  SYM(float, x2, g_x2)
    SYM(__nv_bfloat16, wqhi, g_wqhi) SYM(__nv_bfloat16, wqlo, g_wqlo)
    SYM(__nv_bfloat16, wkhi, g_wkhi) SYM(__nv_bfloat16, wklo, g_wklo)
    SYM(__nv_bfloat16, wvhi, g_wvhi) SYM(__nv_bfloat16, wvlo, g_wvlo)
    SYM(__nv_bfloat16, wohi, g_wohi) SYM(__nv_bfloat16, wolo, g_wolo)
    SYM(__nv_bfloat16, w1hi, g_w1hi) SYM(__nv_bfloat16, w1lo, g_w1lo)
    SYM(__nv_bfloat16, w2hi, g_w2hi) SYM(__nv_bfloat16, w2lo, g_w2lo)
    SYM(float, kvp, g_kvp) SYM(float, ksp, g_ksp)
    #undef SYM

    cudaFuncSetAttribute(gemm_qkv,     cudaFuncAttributeMaxDynamicSharedMemorySize, GEMM_SMEM);
    cudaFuncSetAttribute(gemm3bf<3,0>, cudaFuncAttributeMaxDynamicSharedMemorySize, GEMM_SMEM);
    cudaFuncSetAttribute(gemm3bf<2,1>, cudaFuncAttributeMaxDynamicSharedMemorySize, GEMM_SMEM);

    // 1. fused weight conversion (single launch)
    const int total4 = 4 * NE4 + 2 * NF4;
    cvt_all_kernel<<<total4 / 256, 256>>>(Wq, Wk, Wv, Wo, W1, W2,
        wqhi, wqlo, wkhi, wklo, wvhi, wvlo, wohi, wolo, w1hi, w1lo, w2hi, w2lo);
    // 2. LN1 -> h hi/lo
    ln_hilo_kernel<<<MM, 256>>>(x, ln1_g, ln1_b, hhi, hlo);
    // 3. fused QKV projection (elu+1 on q,k)
    gemm_qkv<<<dim3(24, MM / 128), 256, GEMM_SMEM>>>(hhi, hlo,
        wqhi, wqlo, wkhi, wklo, wvhi, wvlo, bq, bk, bv, q, k, v);
    // 4. linear attention
    attn_kv_kernel<<<dim3(BB * HH, 4), 256>>>(k, v, kvp, ksp);
    attn_out_kernel<<<dim3(LL / 256, BB * HH), 256>>>(q, kvp, ksp, aohi, aolo);
    // 5. Wo projection + residual -> x2   (ncu -s 5 lands here)
    gemm3bf<3,0><<<dim3(EE / 128, MM / 128), 256, GEMM_SMEM>>>(aohi, aolo, wohi, wolo,
        bo, x, x2, nullptr, nullptr, MM, EE, EE);
    // 6. LN2 -> h hi/lo (reuse)
    ln_hilo_kernel<<<MM, 256>>>(x2, ln2_g, ln2_b, hhi, hlo);
    // 7. FFN
    gemm3bf<2,1><<<dim3(FF / 128, MM / 128), 256, GEMM_SMEM>>>(hhi, hlo, w1hi, w1lo,
        b1, nullptr, nullptr, f1hi, f1lo, MM, FF, EE);
    gemm3bf<3,0><<<dim3(EE / 128, MM / 128), 256, GEMM_SMEM>>>(f1hi, f1lo, w2hi, w2lo,
        b2, x2, out, nullptr, nullptr, MM, EE, FF);
}

// round 6
// speedup vs baseline: 1.6074x; 1.3798x over previous
#include <cuda_runtime.h>
#include <cuda_fp16.h>
#include <math.h>
#include <stdint.h>

// Problem dims (fixed)
#define BB 8
#define LL 2048
#define EE 1024
#define HH 16
#define DD 64
#define MM (BB*LL)      // 16384 rows
#define FF (4*EE)       // 4096 ffn dim

#define LN_EPS 1e-5f
#define ATTN_EPS 1e-6f

// ======================= helpers =======================
__device__ __forceinline__ uint32_t smem_to_u32(const void* smem_ptr) {
    uint32_t addr;
    asm("{ .reg .u64 tmp; cvta.to.shared.u64 tmp, %1; cvt.u32.u64 %0, tmp; }"
        : "=r"(addr) : "l"(smem_ptr));
    return addr;
}

__device__ __forceinline__ void cp_async16(uint32_t saddr, const void* gptr) {
    asm volatile("cp.async.cg.shared.global [%0], [%1], 16;" :: "r"(saddr), "l"(gptr));
}
__device__ __forceinline__ void cp_commit() {
    asm volatile("cp.async.commit_group;");
}
template<int N>
__device__ __forceinline__ void cp_wait() {
    asm volatile("cp.async.wait_group %0;" :: "n"(N));
}

__device__ __forceinline__ void ldmatrix_x4(uint32_t* r, uint32_t addr) {
    asm volatile("ldmatrix.sync.aligned.m8n8.x4.shared.b16 {%0,%1,%2,%3}, [%4];"
                 : "=r"(r[0]), "=r"(r[1]), "=r"(r[2]), "=r"(r[3]) : "r"(addr));
}

__device__ __forceinline__ void mma16816(float* c, const uint32_t* a, uint32_t b0, uint32_t b1) {
    asm volatile(
        "mma.sync.aligned.m16n8k16.row.col.f32.f16.f16.f32 "
        "{%0,%1,%2,%3}, {%4,%5,%6,%7}, {%8,%9}, {%0,%1,%2,%3};"
        : "+f"(c[0]), "+f"(c[1]), "+f"(c[2]), "+f"(c[3])
        : "r"(a[0]), "r"(a[1]), "r"(a[2]), "r"(a[3]), "r"(b0), "r"(b1));
}

// ======================= scratch (device globals) =======================
__device__ __align__(256) __half g_hhi [(size_t)MM * EE];
__device__ __align__(256) __half g_hlo [(size_t)MM * EE];
__device__ __align__(256) __half g_aohi[(size_t)MM * EE];
__device__ __align__(256) __half g_aolo[(size_t)MM * EE];
__device__ __align__(256) __half g_f1hi[(size_t)MM * FF];
__device__ __align__(256) __half g_f1lo[(size_t)MM * FF];
__device__ __align__(256) float g_q [(size_t)MM * EE];
__device__ __align__(256) float g_k [(size_t)MM * EE];
__device__ __align__(256) float g_v [(size_t)MM * EE];
__device__ __align__(256) float g_x2[(size_t)MM * EE];
__device__ __align__(256) __half g_wq[(size_t)EE*EE];
__device__ __align__(256) __half g_wk[(size_t)EE*EE];
__device__ __align__(256) __half g_wv[(size_t)EE*EE];
__device__ __align__(256) __half g_wo[(size_t)EE*EE];
__device__ __align__(256) __half g_w1[(size_t)FF*EE];
__device__ __align__(256) __half g_w2[(size_t)EE*FF];
__device__ __align__(256) float g_kvp[4 * BB * HH * DD * DD]; // partial KV
__device__ __align__(256) float g_ksp[4 * BB * HH * DD];      // partial Ksum

// ======================= fused fp32 -> fp16 weight conversion =======================
#define NE4 (EE*EE/4)
#define NF4 (EE*FF/4)
__global__ void cvt_all_kernel(
    const float* __restrict__ Wq, const float* __restrict__ Wk,
    const float* __restrict__ Wv, const float* __restrict__ Wo,
    const float* __restrict__ W1, const float* __restrict__ W2,
    __half* __restrict__ oq, __half* __restrict__ ok2,
    __half* __restrict__ ov, __half* __restrict__ oo,
    __half* __restrict__ o1, __half* __restrict__ o2)
{
    int i = blockIdx.x * 256 + threadIdx.x;
    const float* s; __half* d; int off;
    if (i < 4 * NE4) {
        int w = i / NE4; off = i - w * NE4;
        s = (w == 0) ? Wq : (w == 1) ? Wk : (w == 2) ? Wv : Wo;
        d = (w == 0) ? oq : (w == 1) ? ok2 : (w == 2) ? ov : oo;
    } else {
        int j = i - 4 * NE4;
        int w = j / NF4; off = j - w * NF4;
        s = (w == 0) ? W1 : W2;
        d = (w == 0) ? o1 : o2;
    }
    float4 v = ((const float4*)s)[off];
    ((__half2*)d)[2*off]   = __halves2half2(__float2half(v.x), __float2half(v.y));
    ((__half2*)d)[2*off+1] = __halves2half2(__float2half(v.z), __float2half(v.w));
}

// ======================= LayerNorm (writes fp16 hi/lo) =======================
__global__ void ln_hilo_kernel(const float* __restrict__ x,
                               const float* __restrict__ g,
                               const float* __restrict__ b,
                               __half* __restrict__ yhi,
                               __half* __restrict__ ylo)
{
    const int row = blockIdx.x;
    const int tid = threadIdx.x;
    const float4* xr = (const float4*)(x + (size_t)row * EE);
    float4 v = xr[tid];
    float s  = v.x + v.y + v.z + v.w;
    float sq = v.x*v.x + v.y*v.y + v.z*v.z + v.w*v.w;

    #pragma unroll
    for (int off = 16; off > 0; off >>= 1) {
        s  += __shfl_xor_sync(0xffffffffu, s,  off);
        sq += __shfl_xor_sync(0xffffffffu, sq, off);
    }
    __shared__ float ws[8], wsq[8];
    __shared__ float s_mean, s_rstd;
    const int wid = tid >> 5, lane = tid & 31;
    if (lane == 0) { ws[wid] = s; wsq[wid] = sq; }
    __syncthreads();
    if (tid == 0) {
        float ts = 0.f, tsq = 0.f;
        #pragma unroll
        for (int i = 0; i < 8; i++) { ts += ws[i]; tsq += wsq[i]; }
        float mean = ts * (1.0f / EE);
        float var  = tsq * (1.0f / EE) - mean * mean;
        s_mean = mean;
        s_rstd = rsqrtf(var + LN_EPS);
    }
    __syncthreads();
    const float mean = s_mean, rstd = s_rstd;
    float4 gg = ((const float4*)g)[tid];
    float4 bb = ((const float4*)b)[tid];
    float o0 = (v.x - mean) * rstd * gg.x + bb.x;
    float o1 = (v.y - mean) * rstd * gg.y + bb.y;
    float o2 = (v.z - mean) * rstd * gg.z + bb.z;
    float o3 = (v.w - mean) * rstd * gg.w + bb.w;
    __half h0 = __float2half(o0), h1 = __float2half(o1);
    __half h2 = __float2half(o2), h3 = __float2half(o3);
    __half2* hp = (__half2*)(yhi + (size_t)row * EE + tid * 4);
    __half2* lp = (__half2*)(ylo + (size_t)row * EE + tid * 4);
    hp[0] = __halves2half2(h0, h1);
    hp[1] = __halves2half2(h2, h3);
    lp[0] = __halves2half2(__float2half(o0 - __half2float(h0)),
                           __float2half(o1 - __half2float(h1)));
    lp[1] = __halves2half2(__float2half(o2 - __half2float(h2)),
                           __float2half(o3 - __half2float(h3)));
}

// ======================= mma.sync 2xFP16 GEMM =======================
// C[M,N] = epi((A_hi+A_lo)[M,K] @ fp16(W)[N,K]^T + bias (+R))
// CTA 128x128, 8 warps (2x4), warp tile 64x32, K-chunk 32, 3-stage cp.async ring.
#define STAGE_BYTES 24576
#define OFF_AHI 0
#define OFF_ALO 8192
#define OFF_B   16384
#define GEMM_SMEM (3*STAGE_BYTES)

__device__ __forceinline__ uint32_t swz(int row, int c) {
    return (uint32_t)(row * 64 + ((c ^ ((row >> 1) & 3)) << 4));
}

// Mainloop shared by both GEMM kernels. Requires smem_u, gAhi,gAlo,gB, K, tid, lane,
// warp_m, warp_n in scope.
#define GEMM_MAINLOOP(ACC)                                                              \
    const int nc = K >> 5;                                                              \
    const int lrow = tid >> 2, lc = tid & 3;                                            \
    auto issue_stage = [&](int c) {                                                     \
        if (c < nc) {                                                                   \
            const uint32_t sb = smem_u + (c % 3) * STAGE_BYTES;                         \
            const int k0 = c * 32;                                                      \
            _Pragma("unroll")                                                           \
            for (int i = 0; i < 2; i++) {                                               \
                const int row = lrow + i * 64;                                          \
                const uint32_t so = swz(row, lc);                                       \
                const size_t go = (size_t)row * K + k0 + lc * 8;                        \
                cp_async16(sb + OFF_AHI + so, gAhi + go);                               \
                cp_async16(sb + OFF_ALO + so, gAlo + go);                               \
                cp_async16(sb + OFF_B   + so, gB   + go);                               \
            }                                                                           \
        }                                                                               \
        cp_commit();                                                                    \
    };                                                                                  \
    issue_stage(0); issue_stage(1);                                                     \
    const int lm_r = ((lane >> 3) & 1) * 8 + (lane & 7);                                \
    const int lm_c = lane >> 4;                                                         \
    for (int c = 0; c < nc; c++) {                                                      \
        cp_wait<1>();                                                                   \
        __syncthreads();                                                                \
        issue_stage(c + 2);                                                             \
        const uint32_t sb = smem_u + (c % 3) * STAGE_BYTES;                             \
        _Pragma("unroll")                                                               \
        for (int s = 0; s < 2; s++) {                                                   \
            const int chunk = 2 * s + lm_c;                                             \
            uint32_t Bf[2][4];                                                          \
            _Pragma("unroll")                                                           \
            for (int p = 0; p < 2; p++) {                                               \
                const int row = warp_n + p * 16 + lm_r;                                 \
                ldmatrix_x4(Bf[p], sb + OFF_B + swz(row, chunk));                       \
            }                                                                           \
            _Pragma("unroll")                                                           \
            for (int mi = 0; mi < 4; mi++) {                                            \
                const int row = warp_m + mi * 16 + lm_r;                                \
                uint32_t Ah[4], Al[4];                                                  \
                const uint32_t a = sb + OFF_AHI + swz(row, chunk);                      \
                ldmatrix_x4(Ah, a);                                                     \
                ldmatrix_x4(Al, a + (OFF_ALO - OFF_AHI));                               \
                _Pragma("unroll")                                                       \
                for (int ni = 0; ni < 4; ni++) {                                        \
                    const int p = ni >> 1, q = ni & 1;                                  \
                    mma16816(ACC[mi][ni], Ah, Bf[p][q], Bf[p][2 + q]);                  \
                    mma16816(ACC[mi][ni], Al, Bf[p][q], Bf[p][2 + q]);                  \
                }                                                                       \
            }                                                                           \
        }                                                                               \
    }

template<int EPI, int OUT>   // EPI: 0 none, 2 relu, 3 +residual ; OUT: 0 fp32, 1 fp16 hi/lo
__global__ void __launch_bounds__(256, 2)
gemm2fp(const __half* __restrict__ Ahi, const __half* __restrict__ Alo,
        const __half* __restrict__ Bw,
        const float* __restrict__ bias, const float* __restrict__ Rres,
        float* __restrict__ Cf, __half* __restrict__ Chi, __half* __restrict__ Clo,
        int M, int N, int K)
{
    extern __shared__ __align__(128) char smem[];
    const uint32_t smem_u = smem_to_u32(smem);

    const int tid = threadIdx.x;
    const int wid = tid >> 5, lane = tid & 31;
    const int bm = blockIdx.y, bn = blockIdx.x;
    const int warp_m = (wid >> 2) * 64;
    const int warp_n = (wid & 3) * 32;

    const __half* gAhi = Ahi + (size_t)(bm * 128) * K;
    const __half* gAlo = Alo + (size_t)(bm * 128) * K;
    const __half* gB   = Bw  + (size_t)(bn * 128) * K;

    float acc[4][4][4];
    #pragma unroll
    for (int i = 0; i < 4; i++)
        #pragma unroll
        for (int j = 0; j < 4; j++)
            #pragma unroll
            for (int t = 0; t < 4; t++) acc[i][j][t] = 0.f;

    GEMM_MAINLOOP(acc)

    // ---------------- epilogue ----------------
    const int g = lane >> 2, tig = lane & 3;
    #pragma unroll
    for (int ni = 0; ni < 4; ni++) {
        const int n = bn * 128 + warp_n + ni * 8 + tig * 2;
        const float b0 = __ldg(bias + n), b1 = __ldg(bias + n + 1);
        #pragma unroll
        for (int mi = 0; mi < 4; mi++) {
            const int m0 = bm * 128 + warp_m + mi * 16 + g;
            #pragma unroll
            for (int half = 0; half < 2; half++) {
                const int m = m0 + half * 8;
                float v0 = acc[mi][ni][half * 2 + 0] + b0;
                float v1 = acc[mi][ni][half * 2 + 1] + b1;
                if (EPI == 2) { v0 = fmaxf(v0, 0.f); v1 = fmaxf(v1, 0.f); }
                else if (EPI == 3) {
                    const float2 rv = *(const float2*)(Rres + (size_t)m * N + n);
                    v0 += rv.x; v1 += rv.y;
                }
                if (OUT == 0) {
                    *(float2*)(Cf + (size_t)m * N + n) = make_float2(v0, v1);
                } else {
                    __half h0 = __float2half(v0);
                    __half h1 = __float2half(v1);
                    *(__half2*)(Chi + (size_t)m * N + n) = __halves2half2(h0, h1);
                    *(__half2*)(Clo + (size_t)m * N + n) = __halves2half2(
                        __float2half(v0 - __half2float(h0)),
                        __float2half(v1 - __half2float(h1)));
                }
            }
        }
    }
}

// ---- fused QKV GEMM: bnL in [0,24); w = bnL>>3 selects Wq/Wk/Wv; elu+1 on q,k ----
__global__ void __launch_bounds__(256, 2)
gemm_qkv(const __half* __restrict__ Ahi, const __half* __restrict__ Alo,
         const __half* __restrict__ wq, const __half* __restrict__ wk,
         const __half* __restrict__ wv,
         const float* __restrict__ bqp, const float* __restrict__ bkp,
         const float* __restrict__ bvp,
         float* __restrict__ oq, float* __restrict__ ok, float* __restrict__ ov)
{
    extern __shared__ __align__(128) char smem[];
    const uint32_t smem_u = smem_to_u32(smem);
    const int K = EE, N = EE;

    const int tid = threadIdx.x;
    const int wid = tid >> 5, lane = tid & 31;
    const int bm = blockIdx.y, bnL = blockIdx.x;
    const int w = bnL >> 3, bn = bnL & 7;
    const int warp_m = (wid >> 2) * 64;
    const int warp_n = (wid & 3) * 32;

    const __half* Bw = (w == 0) ? wq : (w == 1) ? wk : wv;
    const float* bias = (w == 0) ? bqp : (w == 1) ? bkp : bvp;
    float* Cf = (w == 0) ? oq : (w == 1) ? ok : ov;
    const bool do_elu = (w < 2);

    const __half* gAhi = Ahi + (size_t)(bm * 128) * K;
    const __half* gAlo = Alo + (size_t)(bm * 128) * K;
    const __half* gB   = Bw  + (size_t)(bn * 128) * K;

    float acc[4][4][4];
    #pragma unroll
    for (int i = 0; i < 4; i++)
        #pragma unroll
        for (int j = 0; j < 4; j++)
            #pragma unroll
            for (int t = 0; t < 4; t++) acc[i][j][t] = 0.f;

    GEMM_MAINLOOP(acc)

    const int g = lane >> 2, tig = lane & 3;
    #pragma unroll
    for (int ni = 0; ni < 4; ni++) {
        const int n = bn * 128 + warp_n + ni * 8 + tig * 2;
        const float b0 = __ldg(bias + n), b1 = __ldg(bias + n + 1);
        #pragma unroll
        for (int mi = 0; mi < 4; mi++) {
            const int m0 = bm * 128 + warp_m + mi * 16 + g;
            #pragma unroll
            for (int half = 0; half < 2; half++) {
                const int m = m0 + half * 8;
                float v0 = acc[mi][ni][half * 2 + 0] + b0;
                float v1 = acc[mi][ni][half * 2 + 1] + b1;
                if (do_elu) {
                    v0 = (v0 > 0.f) ? (v0 + 1.f) : expf(v0);
                    v1 = (v1 > 0.f) ? (v1 + 1.f) : expf(v1);
                }
                *(float2*)(Cf + (size_t)m * N + n) = make_float2(v0, v1);
            }
        }
    }
}

// ======================= attention stage 1: partial KV over 4 L-slices =======================
__global__ void __launch_bounds__(256)
attn_kv_kernel(const float* __restrict__ Kf, const float* __restrict__ Vf,
               float* __restrict__ KVp, float* __restrict__ Ksp)
{
    const int bh = blockIdx.x;
    const int part = blockIdx.y;
    const int b = bh >> 4, h = bh & 15;
    __shared__ float Ks[64][68];
    __shared__ float Vs[64][68];
    const int tid = threadIdx.x;
    const int d0 = (tid >> 4) * 4, m0 = (tid & 15) * 4;

    float acc[4][4];
    #pragma unroll
    for (int i = 0; i < 4; i++)
        #pragma unroll
        for (int j = 0; j < 4; j++) acc[i][j] = 0.f;
    float ksacc = 0.f;

    const size_t base0 = ((size_t)b * LL) * EE + h * DD;
    const int s_begin = part * (LL / 4), s_end = s_begin + LL / 4;

    for (int s0 = s_begin; s0 < s_end; s0 += 64) {
        #pragma unroll
        for (int j = 0; j < 4; j++) {
            const int id = tid + j * 256;
            const int r = id >> 4, c4 = id & 15;
            const size_t ga = base0 + (size_t)(s0 + r) * EE + c4 * 4;
            float4 kk = *(const float4*)(Kf + ga);
            float4 vv = *(const float4*)(Vf + ga);
            Ks[r][c4*4+0]=kk.x; Ks[r][c4*4+1]=kk.y; Ks[r][c4*4+2]=kk.z; Ks[r][c4*4+3]=kk.w;
            Vs[r][c4*4+0]=vv.x; Vs[r][c4*4+1]=vv.y; Vs[r][c4*4+2]=vv.z; Vs[r][c4*4+3]=vv.w;
        }
        __syncthreads();

        if (tid < 64) {
            #pragma unroll 8
            for (int s = 0; s < 64; s++) ksacc += Ks[s][tid];
        }
        #pragma unroll 4
        for (int s = 0; s < 64; s++) {
            float4 kd = *(const float4*)&Ks[s][d0];
            float4 vm = *(const float4*)&Vs[s][m0];
            float ka[4] = {kd.x, kd.y, kd.z, kd.w};
            float va[4] = {vm.x, vm.y, vm.z, vm.w};
            #pragma unroll
            for (int i = 0; i < 4; i++)
                #pragma unroll
                for (int j = 0; j < 4; j++)
                    acc[i][j] += ka[i] * va[j];
        }
        __syncthreads();
    }

    float* kvdst = KVp + ((size_t)(part * (BB*HH) + bh) * DD) * DD;
    #pragma unroll
    for (int i = 0; i < 4; i++)
        *(float4*)(kvdst + (size_t)(d0 + i) * DD + m0) =
            make_float4(acc[i][0], acc[i][1], acc[i][2], acc[i][3]);
    if (tid < 64) Ksp[(part * (BB*HH) + bh) * DD + tid] = ksacc;
}

// ======================= attention stage 2 (sums partials; writes fp16 hi/lo) =======================
__global__ void __launch_bounds__(256)
attn_out_kernel(const float* __restrict__ Qf, const float* __restrict__ KVp,
                const float* __restrict__ Ksp,
                __half* __restrict__ Ohi, __half* __restrict__ Olo)
{
    const int bh = blockIdx.y;
    const int b = bh >> 4, h = bh & 15;
    const int tid = threadIdx.x;
    __shared__ float KVs[64][64];
    __shared__ float ks[64];

    #pragma unroll
    for (int j = 0; j < 4; j++) {
        const int id = tid + j * 256;
        float4 a = make_float4(0.f, 0.f, 0.f, 0.f);
        #pragma unroll
        for (int part = 0; part < 4; part++) {
            float4 p = ((const float4*)(KVp + (size_t)(part * (BB*HH) + bh) * DD * DD))[id];
            a.x += p.x; a.y += p.y; a.z += p.z; a.w += p.w;
        }
        ((float4*)&KVs[0][0])[id] = a;
    }
    if (tid < 16) {
        float4 a = make_float4(0.f, 0.f, 0.f, 0.f);
        #pragma unroll
        for (int part = 0; part < 4; part++) {
            float4 p = ((const float4*)(Ksp + (part * (BB*HH) + bh) * DD))[tid];
            a.x += p.x; a.y += p.y; a.z += p.z; a.w += p.w;
        }
        ((float4*)ks)[tid] = a;
    }
    __syncthreads();

    const int row = b * LL + blockIdx.x * 256 + tid;
    const float4* qrow = (const float4*)(Qf + (size_t)row * EE + h * DD);

    float z = 0.f;
    #pragma unroll
    for (int d4 = 0; d4 < 16; d4++) {
        float4 qv = qrow[d4];
        float4 kv = ((const float4*)ks)[d4];
        z += qv.x*kv.x + qv.y*kv.y + qv.z*kv.z + qv.w*kv.w;
    }
    const float zi = 1.0f / (z + ATTN_EPS);

    float acc[64];
    #pragma unroll
    for (int j = 0; j < 64; j++) acc[j] = 0.f;

    for (int d4 = 0; d4 < 16; d4++) {
        float4 qv = qrow[d4];
        float qs[4] = {qv.x, qv.y, qv.z, qv.w};
        #pragma unroll
        for (int dd = 0; dd < 4; dd++) {
            const float qd = qs[dd];
            const float4* kvr = (const float4*)&KVs[d4 * 4 + dd][0];
            #pragma unroll
            for (int j4 = 0; j4 < 16; j4++) {
                float4 kv = kvr[j4];
                acc[j4*4+0] += qd * kv.x;
                acc[j4*4+1] += qd * kv.y;
                acc[j4*4+2] += qd * kv.z;
                acc[j4*4+3] += qd * kv.w;
            }
        }
    }

    __half* hp = Ohi + (size_t)row * EE + h * DD;
    __half* lp = Olo + (size_t)row * EE + h * DD;
    #pragma unroll
    for (int j2 = 0; j2 < 32; j2++) {
        float a0 = acc[j2*2]   * zi;
        float a1 = acc[j2*2+1] * zi;
        __half h0 = __float2half(a0);
        __half h1 = __float2half(a1);
        ((__half2*)hp)[j2] = __halves2half2(h0, h1);
        ((__half2*)lp)[j2] = __halves2half2(
            __float2half(a0 - __half2float(h0)),
            __float2half(a1 - __half2float(h1)));
    }
}

// ======================= host launcher =======================
extern "C" void kernel_launch(void* const* d_in, const int* in_sizes, int n_in,
                              void* d_out, int out_size)
{
    const float* x     = (const float*)d_in[0];
    const float* ln1_g = (const float*)d_in[1];
    const float* ln1_b = (const float*)d_in[2];
    const float* ln2_g = (const float*)d_in[3];
    const float* ln2_b = (const float*)d_in[4];
    const float* Wq = (const float*)d_in[5];  const float* bq = (const float*)d_in[6];
    const float* Wk = (const float*)d_in[7];  const float* bk = (const float*)d_in[8];
    const float* Wv = (const float*)d_in[9];  const float* bv = (const float*)d_in[10];
    const float* Wo = (const float*)d_in[11]; const float* bo = (const float*)d_in[12];
    const float* W1 = (const float*)d_in[13]; const float* b1 = (const float*)d_in[14];
    const float* W2 = (const float*)d_in[15]; const float* b2 = (const float*)d_in[16];
    float* out = (float*)d_out;

    #define SYM(T, name, sym) T* name; { void* p; cudaGetSymbolAddress(&p, sym); name = (T*)p; }
    SYM(__half, hhi, g_hhi)  SYM(__half, hlo, g_hlo)
    SYM(__half, aohi, g_aohi) SYM(__half, aolo, g_aolo)
    SYM(__half, f1hi, g_f1hi) SYM(__half, f1lo, g_f1lo)
    SYM(float, q, g_q)  SYM(float, k, g_k)  SYM(float, v, g_v)  SYM(float, x2, g_x2)
    SYM(__half, wq, g_wq) SYM(__half, wk, g_wk) SYM(__half, wv, g_wv)
    SYM(__half, wo, g_wo) SYM(__half, w1, g_w1) SYM(__half, w2, g_w2)
    SYM(float, kvp, g_kvp) SYM(float, ksp, g_ksp)
    #undef SYM

    cudaFuncSetAttribute(gemm_qkv,     cudaFuncAttributeMaxDynamicSharedMemorySize, GEMM_SMEM);
    cudaFuncSetAttribute(gemm2fp<3,0>, cudaFuncAttributeMaxDynamicSharedMemorySize, GEMM_SMEM);
    cudaFuncSetAttribute(gemm2fp<2,1>, cudaFuncAttributeMaxDynamicSharedMemorySize, GEMM_SMEM);

    // 1. fused weight conversion (single launch)
    const int total4 = 4 * NE4 + 2 * NF4;
    cvt_all_kernel<<<total4 / 256, 256>>>(Wq, Wk, Wv, Wo, W1, W2,
        wq, wk, wv, wo, w1, w2);
    // 2. LN1 -> h hi/lo
    ln_hilo_kernel<<<MM, 256>>>(x, ln1_g, ln1_b, hhi, hlo);
    // 3. fused QKV projection (elu+1 on q,k)
    gemm_qkv<<<dim3(24, MM / 128), 256, GEMM_SMEM>>>(hhi, hlo,
        wq, wk, wv, bq, bk, bv, q, k, v);
    // 4. linear attention
    attn_kv_kernel<<<dim3(BB * HH, 4), 256>>>(k, v, kvp, ksp);
    attn_out_kernel<<<dim3(LL / 256, BB * HH), 256>>>(q, kvp, ksp, aohi, aolo);
    // 5. Wo projection + residual -> x2
    gemm2fp<3,0><<<dim3(EE / 128, MM / 128), 256, GEMM_SMEM>>>(aohi, aolo, wo,
        bo, x, x2, nullptr, nullptr, MM, EE, EE);
    // 6. LN2 -> h hi/lo (reuse)
    ln_hilo_kernel<<<MM, 256>>>(x2, ln2_g, ln2_b, hhi, hlo);
    // 7. FFN
    gemm2fp<2,1><<<dim3(FF / 128, MM / 128), 256, GEMM_SMEM>>>(hhi, hlo, w1,
        b1, nullptr, nullptr, f1hi, f1lo, MM, FF, EE);
    gemm2fp<3,0><<<dim3(EE / 128, MM / 128), 256, GEMM_SMEM>>>(f1hi, f1lo, w2,
        b2, x2, out, nullptr, nullptr, MM, EE, FF);
}

// round 7
// speedup vs baseline: 2.8153x; 1.7515x over previous
#include <cuda_runtime.h>
#include <cuda_fp16.h>
#include <math.h>
#include <stdint.h>

// Problem dims (fixed)
#define BB 8
#define LL 2048
#define EE 1024
#define HH 16
#define DD 64
#define MM (BB*LL)      // 16384 rows
#define FF (4*EE)       // 4096 ffn dim

#define LN_EPS 1e-5f
#define ATTN_EPS 1e-6f

// ======================= helpers =======================
__device__ __forceinline__ uint32_t smem_to_u32(const void* smem_ptr) {
    uint32_t addr;
    asm("{ .reg .u64 tmp; cvta.to.shared.u64 tmp, %1; cvt.u32.u64 %0, tmp; }"
        : "=r"(addr) : "l"(smem_ptr));
    return addr;
}

__device__ __forceinline__ void cp_async16(uint32_t saddr, const void* gptr) {
    asm volatile("cp.async.cg.shared.global [%0], [%1], 16;" :: "r"(saddr), "l"(gptr));
}
__device__ __forceinline__ void cp_commit() {
    asm volatile("cp.async.commit_group;");
}
template<int N>
__device__ __forceinline__ void cp_wait() {
    asm volatile("cp.async.wait_group %0;" :: "n"(N));
}

__device__ __forceinline__ void ldmatrix_x4(uint32_t* r, uint32_t addr) {
    asm volatile("ldmatrix.sync.aligned.m8n8.x4.shared.b16 {%0,%1,%2,%3}, [%4];"
                 : "=r"(r[0]), "=r"(r[1]), "=r"(r[2]), "=r"(r[3]) : "r"(addr));
}

__device__ __forceinline__ void mma16816(float* c, const uint32_t* a, uint32_t b0, uint32_t b1) {
    asm volatile(
        "mma.sync.aligned.m16n8k16.row.col.f32.f16.f16.f32 "
        "{%0,%1,%2,%3}, {%4,%5,%6,%7}, {%8,%9}, {%0,%1,%2,%3};"
        : "+f"(c[0]), "+f"(c[1]), "+f"(c[2]), "+f"(c[3])
        : "r"(a[0]), "r"(a[1]), "r"(a[2]), "r"(a[3]), "r"(b0), "r"(b1));
}

// ======================= scratch (device globals) =======================
__device__ __align__(256) __half g_h  [(size_t)MM * EE];   // LN out (fp16)
__device__ __align__(256) __half g_ao [(size_t)MM * EE];   // attn out (fp16)
__device__ __align__(256) __half g_f1 [(size_t)MM * FF];   // ffn mid (fp16)
__device__ __align__(256) float g_q [(size_t)MM * EE];
__device__ __align__(256) float g_k [(size_t)MM * EE];
__device__ __align__(256) float g_v [(size_t)MM * EE];
__device__ __align__(256) float g_x2[(size_t)MM * EE];
__device__ __align__(256) __half g_wq[(size_t)EE*EE];
__device__ __align__(256) __half g_wk[(size_t)EE*EE];
__device__ __align__(256) __half g_wv[(size_t)EE*EE];
__device__ __align__(256) __half g_wo[(size_t)EE*EE];
__device__ __align__(256) __half g_w1[(size_t)FF*EE];
__device__ __align__(256) __half g_w2[(size_t)EE*FF];
__device__ __align__(256) float g_kvp[4 * BB * HH * DD * DD]; // partial KV
__device__ __align__(256) float g_ksp[4 * BB * HH * DD];      // partial Ksum

// ======================= fused fp32 -> fp16 weight conversion =======================
#define NE4 (EE*EE/4)
#define NF4 (EE*FF/4)
__global__ void cvt_all_kernel(
    const float* __restrict__ Wq, const float* __restrict__ Wk,
    const float* __restrict__ Wv, const float* __restrict__ Wo,
    const float* __restrict__ W1, const float* __restrict__ W2,
    __half* __restrict__ oq, __half* __restrict__ ok2,
    __half* __restrict__ ov, __half* __restrict__ oo,
    __half* __restrict__ o1, __half* __restrict__ o2)
{
    int i = blockIdx.x * 256 + threadIdx.x;
    const float* s; __half* d; int off;
    if (i < 4 * NE4) {
        int w = i / NE4; off = i - w * NE4;
        s = (w == 0) ? Wq : (w == 1) ? Wk : (w == 2) ? Wv : Wo;
        d = (w == 0) ? oq : (w == 1) ? ok2 : (w == 2) ? ov : oo;
    } else {
        int j = i - 4 * NE4;
        int w = j / NF4; off = j - w * NF4;
        s = (w == 0) ? W1 : W2;
        d = (w == 0) ? o1 : o2;
    }
    float4 v = ((const float4*)s)[off];
    ((__half2*)d)[2*off]   = __halves2half2(__float2half(v.x), __float2half(v.y));
    ((__half2*)d)[2*off+1] = __halves2half2(__float2half(v.z), __float2half(v.w));
}

// ======================= LayerNorm (writes fp16) =======================
__global__ void ln_fp16_kernel(const float* __restrict__ x,
                               const float* __restrict__ g,
                               const float* __restrict__ b,
                               __half* __restrict__ y)
{
    const int row = blockIdx.x;
    const int tid = threadIdx.x;
    const float4* xr = (const float4*)(x + (size_t)row * EE);
    float4 v = xr[tid];
    float s  = v.x + v.y + v.z + v.w;
    float sq = v.x*v.x + v.y*v.y + v.z*v.z + v.w*v.w;

    #pragma unroll
    for (int off = 16; off > 0; off >>= 1) {
        s  += __shfl_xor_sync(0xffffffffu, s,  off);
        sq += __shfl_xor_sync(0xffffffffu, sq, off);
    }
    __shared__ float ws[8], wsq[8];
    __shared__ float s_mean, s_rstd;
    const int wid = tid >> 5, lane = tid & 31;
    if (lane == 0) { ws[wid] = s; wsq[wid] = sq; }
    __syncthreads();
    if (tid == 0) {
        float ts = 0.f, tsq = 0.f;
        #pragma unroll
        for (int i = 0; i < 8; i++) { ts += ws[i]; tsq += wsq[i]; }
        float mean = ts * (1.0f / EE);
        float var  = tsq * (1.0f / EE) - mean * mean;
        s_mean = mean;
        s_rstd = rsqrtf(var + LN_EPS);
    }
    __syncthreads();
    const float mean = s_mean, rstd = s_rstd;
    float4 gg = ((const float4*)g)[tid];
    float4 bb = ((const float4*)b)[tid];
    float o0 = (v.x - mean) * rstd * gg.x + bb.x;
    float o1 = (v.y - mean) * rstd * gg.y + bb.y;
    float o2 = (v.z - mean) * rstd * gg.z + bb.z;
    float o3 = (v.w - mean) * rstd * gg.w + bb.w;
    __half2* hp = (__half2*)(y + (size_t)row * EE + tid * 4);
    hp[0] = __halves2half2(__float2half(o0), __float2half(o1));
    hp[1] = __halves2half2(__float2half(o2), __float2half(o3));
}

// ======================= mma.sync single-pass FP16 GEMM =======================
// C[M,N] = epi(fp16(A)[M,K] @ fp16(W)[N,K]^T + bias (+R))
// CTA 128x128, 8 warps (2x4), warp tile 64x32, K-chunk 32, 4-stage cp.async ring.
#define STAGE_BYTES 16384
#define OFF_A 0
#define OFF_B 8192
#define GEMM_SMEM (4*STAGE_BYTES)

__device__ __forceinline__ uint32_t swz(int row, int c) {
    return (uint32_t)(row * 64 + ((c ^ ((row >> 1) & 3)) << 4));
}

// Mainloop shared by both GEMM kernels. Requires smem_u, gA, gB, K, tid, lane,
// warp_m, warp_n in scope.
#define GEMM_MAINLOOP(ACC)                                                              \
    const int nc = K >> 5;                                                              \
    const int lrow = tid >> 2, lc = tid & 3;                                            \
    auto issue_stage = [&](int c) {                                                     \
        if (c < nc) {                                                                   \
            const uint32_t sb = smem_u + (c & 3) * STAGE_BYTES;                         \
            const int k0 = c * 32;                                                      \
            _Pragma("unroll")                                                           \
            for (int i = 0; i < 2; i++) {                                               \
                const int row = lrow + i * 64;                                          \
                const uint32_t so = swz(row, lc);                                       \
                const size_t go = (size_t)row * K + k0 + lc * 8;                        \
                cp_async16(sb + OFF_A + so, gA + go);                                   \
                cp_async16(sb + OFF_B + so, gB + go);                                   \
            }                                                                           \
        }                                                                               \
        cp_commit();                                                                    \
    };                                                                                  \
    issue_stage(0); issue_stage(1); issue_stage(2);                                     \
    const int lm_r = ((lane >> 3) & 1) * 8 + (lane & 7);                                \
    const int lm_c = lane >> 4;                                                         \
    for (int c = 0; c < nc; c++) {                                                      \
        cp_wait<2>();                                                                   \
        __syncthreads();                                                                \
        issue_stage(c + 3);                                                             \
        const uint32_t sb = smem_u + (c & 3) * STAGE_BYTES;                             \
        _Pragma("unroll")                                                               \
        for (int s = 0; s < 2; s++) {                                                   \
            const int chunk = 2 * s + lm_c;                                             \
            uint32_t Bf[2][4];                                                          \
            _Pragma("unroll")                                                           \
            for (int p = 0; p < 2; p++) {                                               \
                const int row = warp_n + p * 16 + lm_r;                                 \
                ldmatrix_x4(Bf[p], sb + OFF_B + swz(row, chunk));                       \
            }                                                                           \
            _Pragma("unroll")                                                           \
            for (int mi = 0; mi < 4; mi++) {                                            \
                const int row = warp_m + mi * 16 + lm_r;                                \
                uint32_t Af[4];                                                         \
                ldmatrix_x4(Af, sb + OFF_A + swz(row, chunk));                          \
                _Pragma("unroll")                                                       \
                for (int ni = 0; ni < 4; ni++) {                                        \
                    const int p = ni >> 1, q = ni & 1;                                  \
                    mma16816(ACC[mi][ni], Af, Bf[p][q], Bf[p][2 + q]);                  \
                }                                                                       \
            }                                                                           \
        }                                                                               \
    }

template<int EPI, int OUT>   // EPI: 0 none, 2 relu, 3 +residual ; OUT: 0 fp32, 1 fp16
__global__ void __launch_bounds__(256, 2)
gemm1fp(const __half* __restrict__ Aa, const __half* __restrict__ Bw,
        const float* __restrict__ bias, const float* __restrict__ Rres,
        float* __restrict__ Cf, __half* __restrict__ Ch,
        int M, int N, int K)
{
    extern __shared__ __align__(128) char smem[];
    const uint32_t smem_u = smem_to_u32(smem);

    const int tid = threadIdx.x;
    const int wid = tid >> 5, lane = tid & 31;
    const int bm = blockIdx.y, bn = blockIdx.x;
    const int warp_m = (wid >> 2) * 64;
    const int warp_n = (wid & 3) * 32;

    const __half* gA = Aa + (size_t)(bm * 128) * K;
    const __half* gB = Bw + (size_t)(bn * 128) * K;

    float acc[4][4][4];
    #pragma unroll
    for (int i = 0; i < 4; i++)
        #pragma unroll
        for (int j = 0; j < 4; j++)
            #pragma unroll
            for (int t = 0; t < 4; t++) acc[i][j][t] = 0.f;

    GEMM_MAINLOOP(acc)

    // ---------------- epilogue ----------------
    const int g = lane >> 2, tig = lane & 3;
    #pragma unroll
    for (int ni = 0; ni < 4; ni++) {
        const int n = bn * 128 + warp_n + ni * 8 + tig * 2;
        const float b0 = __ldg(bias + n), b1 = __ldg(bias + n + 1);
        #pragma unroll
        for (int mi = 0; mi < 4; mi++) {
            const int m0 = bm * 128 + warp_m + mi * 16 + g;
            #pragma unroll
            for (int half = 0; half < 2; half++) {
                const int m = m0 + half * 8;
                float v0 = acc[mi][ni][half * 2 + 0] + b0;
                float v1 = acc[mi][ni][half * 2 + 1] + b1;
                if (EPI == 2) { v0 = fmaxf(v0, 0.f); v1 = fmaxf(v1, 0.f); }
                else if (EPI == 3) {
                    const float2 rv = *(const float2*)(Rres + (size_t)m * N + n);
                    v0 += rv.x; v1 += rv.y;
                }
                if (OUT == 0) {
                    *(float2*)(Cf + (size_t)m * N + n) = make_float2(v0, v1);
                } else {
                    *(__half2*)(Ch + (size_t)m * N + n) =
                        __halves2half2(__float2half(v0), __float2half(v1));
                }
            }
        }
    }
}

// ---- fused QKV GEMM: bnL in [0,24); w = bnL>>3 selects Wq/Wk/Wv; elu+1 on q,k ----
__global__ void __launch_bounds__(256, 2)
gemm_qkv(const __half* __restrict__ Aa,
         const __half* __restrict__ wq, const __half* __restrict__ wk,
         const __half* __restrict__ wv,
         const float* __restrict__ bqp, const float* __restrict__ bkp,
         const float* __restrict__ bvp,
         float* __restrict__ oq, float* __restrict__ ok, float* __restrict__ ov)
{
    extern __shared__ __align__(128) char smem[];
    const uint32_t smem_u = smem_to_u32(smem);
    const int K = EE, N = EE;

    const int tid = threadIdx.x;
    const int wid = tid >> 5, lane = tid & 31;
    const int bm = blockIdx.y, bnL = blockIdx.x;
    const int w = bnL >> 3, bn = bnL & 7;
    const int warp_m = (wid >> 2) * 64;
    const int warp_n = (wid & 3) * 32;

    const __half* Bw = (w == 0) ? wq : (w == 1) ? wk : wv;
    const float* bias = (w == 0) ? bqp : (w == 1) ? bkp : bvp;
    float* Cf = (w == 0) ? oq : (w == 1) ? ok : ov;
    const bool do_elu = (w < 2);

    const __half* gA = Aa + (size_t)(bm * 128) * K;
    const __half* gB = Bw + (size_t)(bn * 128) * K;

    float acc[4][4][4];
    #pragma unroll
    for (int i = 0; i < 4; i++)
        #pragma unroll
        for (int j = 0; j < 4; j++)
            #pragma unroll
            for (int t = 0; t < 4; t++) acc[i][j][t] = 0.f;

    GEMM_MAINLOOP(acc)

    const int g = lane >> 2, tig = lane & 3;
    #pragma unroll
    for (int ni = 0; ni < 4; ni++) {
        const int n = bn * 128 + warp_n + ni * 8 + tig * 2;
        const float b0 = __ldg(bias + n), b1 = __ldg(bias + n + 1);
        #pragma unroll
        for (int mi = 0; mi < 4; mi++) {
            const int m0 = bm * 128 + warp_m + mi * 16 + g;
            #pragma unroll
            for (int half = 0; half < 2; half++) {
                const int m = m0 + half * 8;
                float v0 = acc[mi][ni][half * 2 + 0] + b0;
                float v1 = acc[mi][ni][half * 2 + 1] + b1;
                if (do_elu) {
                    v0 = (v0 > 0.f) ? (v0 + 1.f) : expf(v0);
                    v1 = (v1 > 0.f) ? (v1 + 1.f) : expf(v1);
                }
                *(float2*)(Cf + (size_t)m * N + n) = make_float2(v0, v1);
            }
        }
    }
}

// ======================= attention stage 1: partial KV over 4 L-slices =======================
__global__ void __launch_bounds__(256)
attn_kv_kernel(const float* __restrict__ Kf, const float* __restrict__ Vf,
               float* __restrict__ KVp, float* __restrict__ Ksp)
{
    const int bh = blockIdx.x;
    const int part = blockIdx.y;
    const int b = bh >> 4, h = bh & 15;
    __shared__ float Ks[64][68];
    __shared__ float Vs[64][68];
    const int tid = threadIdx.x;
    const int d0 = (tid >> 4) * 4, m0 = (tid & 15) * 4;

    float acc[4][4];
    #pragma unroll
    for (int i = 0; i < 4; i++)
        #pragma unroll
        for (int j = 0; j < 4; j++) acc[i][j] = 0.f;
    float ksacc = 0.f;

    const size_t base0 = ((size_t)b * LL) * EE + h * DD;
    const int s_begin = part * (LL / 4), s_end = s_begin + LL / 4;

    for (int s0 = s_begin; s0 < s_end; s0 += 64) {
        #pragma unroll
        for (int j = 0; j < 4; j++) {
            const int id = tid + j * 256;
            const int r = id >> 4, c4 = id & 15;
            const size_t ga = base0 + (size_t)(s0 + r) * EE + c4 * 4;
            float4 kk = *(const float4*)(Kf + ga);
            float4 vv = *(const float4*)(Vf + ga);
            Ks[r][c4*4+0]=kk.x; Ks[r][c4*4+1]=kk.y; Ks[r][c4*4+2]=kk.z; Ks[r][c4*4+3]=kk.w;
            Vs[r][c4*4+0]=vv.x; Vs[r][c4*4+1]=vv.y; Vs[r][c4*4+2]=vv.z; Vs[r][c4*4+3]=vv.w;
        }
        __syncthreads();

        if (tid < 64) {
            #pragma unroll 8
            for (int s = 0; s < 64; s++) ksacc += Ks[s][tid];
        }
        #pragma unroll 4
        for (int s = 0; s < 64; s++) {
            float4 kd = *(const float4*)&Ks[s][d0];
            float4 vm = *(const float4*)&Vs[s][m0];
            float ka[4] = {kd.x, kd.y, kd.z, kd.w};
            float va[4] = {vm.x, vm.y, vm.z, vm.w};
            #pragma unroll
            for (int i = 0; i < 4; i++)
                #pragma unroll
                for (int j = 0; j < 4; j++)
                    acc[i][j] += ka[i] * va[j];
        }
        __syncthreads();
    }

    float* kvdst = KVp + ((size_t)(part * (BB*HH) + bh) * DD) * DD;
    #pragma unroll
    for (int i = 0; i < 4; i++)
        *(float4*)(kvdst + (size_t)(d0 + i) * DD + m0) =
            make_float4(acc[i][0], acc[i][1], acc[i][2], acc[i][3]);
    if (tid < 64) Ksp[(part * (BB*HH) + bh) * DD + tid] = ksacc;
}

// ======================= attention stage 2 (sums partials; writes fp16) =======================
__global__ void __launch_bounds__(256)
attn_out_kernel(const float* __restrict__ Qf, const float* __restrict__ KVp,
                const float* __restrict__ Ksp, __half* __restrict__ Oh)
{
    const int bh = blockIdx.y;
    const int b = bh >> 4, h = bh & 15;
    const int tid = threadIdx.x;
    __shared__ float KVs[64][64];
    __shared__ float ks[64];

    #pragma unroll
    for (int j = 0; j < 4; j++) {
        const int id = tid + j * 256;
        float4 a = make_float4(0.f, 0.f, 0.f, 0.f);
        #pragma unroll
        for (int part = 0; part < 4; part++) {
            float4 p = ((const float4*)(KVp + (size_t)(part * (BB*HH) + bh) * DD * DD))[id];
            a.x += p.x; a.y += p.y; a.z += p.z; a.w += p.w;
        }
        ((float4*)&KVs[0][0])[id] = a;
    }
    if (tid < 16) {
        float4 a = make_float4(0.f, 0.f, 0.f, 0.f);
        #pragma unroll
        for (int part = 0; part < 4; part++) {
            float4 p = ((const float4*)(Ksp + (part * (BB*HH) + bh) * DD))[tid];
            a.x += p.x; a.y += p.y; a.z += p.z; a.w += p.w;
        }
        ((float4*)ks)[tid] = a;
    }
    __syncthreads();

    const int row = b * LL + blockIdx.x * 256 + tid;
    const float4* qrow = (const float4*)(Qf + (size_t)row * EE + h * DD);

    float z = 0.f;
    #pragma unroll
    for (int d4 = 0; d4 < 16; d4++) {
        float4 qv = qrow[d4];
        float4 kv = ((const float4*)ks)[d4];
        z += qv.x*kv.x + qv.y*kv.y + qv.z*kv.z + qv.w*kv.w;
    }
    const float zi = 1.0f / (z + ATTN_EPS);

    float acc[64];
    #pragma unroll
    for (int j = 0; j < 64; j++) acc[j] = 0.f;

    for (int d4 = 0; d4 < 16; d4++) {
        float4 qv = qrow[d4];
        float qs[4] = {qv.x, qv.y, qv.z, qv.w};
        #pragma unroll
        for (int dd = 0; dd < 4; dd++) {
            const float qd = qs[dd];
            const float4* kvr = (const float4*)&KVs[d4 * 4 + dd][0];
            #pragma unroll
            for (int j4 = 0; j4 < 16; j4++) {
                float4 kv = kvr[j4];
                acc[j4*4+0] += qd * kv.x;
                acc[j4*4+1] += qd * kv.y;
                acc[j4*4+2] += qd * kv.z;
                acc[j4*4+3] += qd * kv.w;
            }
        }
    }

    __half* hp = Oh + (size_t)row * EE + h * DD;
    #pragma unroll
    for (int j2 = 0; j2 < 32; j2++) {
        ((__half2*)hp)[j2] = __halves2half2(
            __float2half(acc[j2*2]   * zi),
            __float2half(acc[j2*2+1] * zi));
    }
}

// ======================= host launcher =======================
extern "C" void kernel_launch(void* const* d_in, const int* in_sizes, int n_in,
                              void* d_out, int out_size)
{
    const float* x     = (const float*)d_in[0];
    const float* ln1_g = (const float*)d_in[1];
    const float* ln1_b = (const float*)d_in[2];
    const float* ln2_g = (const float*)d_in[3];
    const float* ln2_b = (const float*)d_in[4];
    const float* Wq = (const float*)d_in[5];  const float* bq = (const float*)d_in[6];
    const float* Wk = (const float*)d_in[7];  const float* bk = (const float*)d_in[8];
    const float* Wv = (const float*)d_in[9];  const float* bv = (const float*)d_in[10];
    const float* Wo = (const float*)d_in[11]; const float* bo = (const float*)d_in[12];
    const float* W1 = (const float*)d_in[13]; const float* b1 = (const float*)d_in[14];
    const float* W2 = (const float*)d_in[15]; const float* b2 = (const float*)d_in[16];
    float* out = (float*)d_out;

    #define SYM(T, name, sym) T* name; { void* p; cudaGetSymbolAddress(&p, sym); name = (T*)p; }
    SYM(__half, h, g_h)  SYM(__half, ao, g_ao)  SYM(__half, f1, g_f1)
    SYM(float, q, g_q)  SYM(float, k, g_k)  SYM(float, v, g_v)  SYM(float, x2, g_x2)
    SYM(__half, wq, g_wq) SYM(__half, wk, g_wk) SYM(__half, wv, g_wv)
    SYM(__half, wo, g_wo) SYM(__half, w1, g_w1) SYM(__half, w2, g_w2)
    SYM(float, kvp, g_kvp) SYM(float, ksp, g_ksp)
    #undef SYM

    cudaFuncSetAttribute(gemm_qkv,     cudaFuncAttributeMaxDynamicSharedMemorySize, GEMM_SMEM);
    cudaFuncSetAttribute(gemm1fp<3,0>, cudaFuncAttributeMaxDynamicSharedMemorySize, GEMM_SMEM);
    cudaFuncSetAttribute(gemm1fp<2,1>, cudaFuncAttributeMaxDynamicSharedMemorySize, GEMM_SMEM);

    // 1. fused weight conversion (single launch)
    const int total4 = 4 * NE4 + 2 * NF4;
    cvt_all_kernel<<<total4 / 256, 256>>>(Wq, Wk, Wv, Wo, W1, W2,
        wq, wk, wv, wo, w1, w2);
    // 2. LN1 -> h (fp16)
    ln_fp16_kernel<<<MM, 256>>>(x, ln1_g, ln1_b, h);
    // 3. fused QKV projection (elu+1 on q,k)
    gemm_qkv<<<dim3(24, MM / 128), 256, GEMM_SMEM>>>(h,
        wq, wk, wv, bq, bk, bv, q, k, v);
    // 4. linear attention
    attn_kv_kernel<<<dim3(BB * HH, 4), 256>>>(k, v, kvp, ksp);
    attn_out_kernel<<<dim3(LL / 256, BB * HH), 256>>>(q, kvp, ksp, ao);
    // 5. Wo projection + residual -> x2
    gemm1fp<3,0><<<dim3(EE / 128, MM / 128), 256, GEMM_SMEM>>>(ao, wo,
        bo, x, x2, nullptr, MM, EE, EE);
    // 6. LN2 -> h (fp16, reuse)
    ln_fp16_kernel<<<MM, 256>>>(x2, ln2_g, ln2_b, h);
    // 7. FFN
    gemm1fp<2,1><<<dim3(FF / 128, MM / 128), 256, GEMM_SMEM>>>(h, w1,
        b1, nullptr, nullptr, f1, MM, FF, EE);
    gemm1fp<3,0><<<dim3(EE / 128, MM / 128), 256, GEMM_SMEM>>>(f1, w2,
        b2, x2, out, nullptr, MM, EE, FF);
}

// round 8
// speedup vs baseline: 2.9525x; 1.0487x over previous
#include <cuda_runtime.h>
#include <cuda_fp16.h>
#include <math.h>
#include <stdint.h>

// Problem dims (fixed)
#define BB 8
#define LL 2048
#define EE 1024
#define HH 16
#define DD 64
#define MM (BB*LL)      // 16384 rows
#define FF (4*EE)       // 4096 ffn dim

#define LN_EPS 1e-5f
#define ATTN_EPS 1e-6f

// ======================= helpers =======================
__device__ __forceinline__ uint32_t smem_to_u32(const void* smem_ptr) {
    uint32_t addr;
    asm("{ .reg .u64 tmp; cvta.to.shared.u64 tmp, %1; cvt.u32.u64 %0, tmp; }"
        : "=r"(addr) : "l"(smem_ptr));
    return addr;
}

__device__ __forceinline__ void cp_async16(uint32_t saddr, const void* gptr) {
    asm volatile("cp.async.cg.shared.global [%0], [%1], 16;" :: "r"(saddr), "l"(gptr));
}
__device__ __forceinline__ void cp_commit() {
    asm volatile("cp.async.commit_group;");
}
template<int N>
__device__ __forceinline__ void cp_wait() {
    asm volatile("cp.async.wait_group %0;" :: "n"(N));
}

__device__ __forceinline__ void ldmatrix_x4(uint32_t* r, uint32_t addr) {
    asm volatile("ldmatrix.sync.aligned.m8n8.x4.shared.b16 {%0,%1,%2,%3}, [%4];"
                 : "=r"(r[0]), "=r"(r[1]), "=r"(r[2]), "=r"(r[3]) : "r"(addr));
}

__device__ __forceinline__ void mma16816(float* c, const uint32_t* a, uint32_t b0, uint32_t b1) {
    asm volatile(
        "mma.sync.aligned.m16n8k16.row.col.f32.f16.f16.f32 "
        "{%0,%1,%2,%3}, {%4,%5,%6,%7}, {%8,%9}, {%0,%1,%2,%3};"
        : "+f"(c[0]), "+f"(c[1]), "+f"(c[2]), "+f"(c[3])
        : "r"(a[0]), "r"(a[1]), "r"(a[2]), "r"(a[3]), "r"(b0), "r"(b1));
}

// ======================= scratch (device globals) =======================
__device__ __align__(256) __half g_h  [(size_t)MM * EE];   // LN out (fp16)
__device__ __align__(256) __half g_ao [(size_t)MM * EE];   // attn out (fp16)
__device__ __align__(256) __half g_f1 [(size_t)MM * FF];   // ffn mid (fp16)
__device__ __align__(256) __half g_q [(size_t)MM * EE];
__device__ __align__(256) __half g_k [(size_t)MM * EE];
__device__ __align__(256) __half g_v [(size_t)MM * EE];
__device__ __align__(256) float g_x2[(size_t)MM * EE];
__device__ __align__(256) __half g_wq[(size_t)EE*EE];
__device__ __align__(256) __half g_wk[(size_t)EE*EE];
__device__ __align__(256) __half g_wv[(size_t)EE*EE];
__device__ __align__(256) __half g_wo[(size_t)EE*EE];
__device__ __align__(256) __half g_w1[(size_t)FF*EE];
__device__ __align__(256) __half g_w2[(size_t)EE*FF];
__device__ __align__(256) float g_kvp[4 * BB * HH * DD * DD]; // partial KV
__device__ __align__(256) float g_ksp[4 * BB * HH * DD];      // partial Ksum

// ======================= fused fp32 -> fp16 weight conversion =======================
#define NE4 (EE*EE/4)
#define NF4 (EE*FF/4)
__global__ void cvt_all_kernel(
    const float* __restrict__ Wq, const float* __restrict__ Wk,
    const float* __restrict__ Wv, const float* __restrict__ Wo,
    const float* __restrict__ W1, const float* __restrict__ W2,
    __half* __restrict__ oq, __half* __restrict__ ok2,
    __half* __restrict__ ov, __half* __restrict__ oo,
    __half* __restrict__ o1, __half* __restrict__ o2)
{
    int i = blockIdx.x * 256 + threadIdx.x;
    const float* s; __half* d; int off;
    if (i < 4 * NE4) {
        int w = i / NE4; off = i - w * NE4;
        s = (w == 0) ? Wq : (w == 1) ? Wk : (w == 2) ? Wv : Wo;
        d = (w == 0) ? oq : (w == 1) ? ok2 : (w == 2) ? ov : oo;
    } else {
        int j = i - 4 * NE4;
        int w = j / NF4; off = j - w * NF4;
        s = (w == 0) ? W1 : W2;
        d = (w == 0) ? o1 : o2;
    }
    float4 v = ((const float4*)s)[off];
    ((__half2*)d)[2*off]   = __halves2half2(__float2half(v.x), __float2half(v.y));
    ((__half2*)d)[2*off+1] = __halves2half2(__float2half(v.z), __float2half(v.w));
}

// ======================= LayerNorm (writes fp16) =======================
__global__ void ln_fp16_kernel(const float* __restrict__ x,
                               const float* __restrict__ g,
                               const float* __restrict__ b,
                               __half* __restrict__ y)
{
    const int row = blockIdx.x;
    const int tid = threadIdx.x;
    const float4* xr = (const float4*)(x + (size_t)row * EE);
    float4 v = xr[tid];
    float s  = v.x + v.y + v.z + v.w;
    float sq = v.x*v.x + v.y*v.y + v.z*v.z + v.w*v.w;

    #pragma unroll
    for (int off = 16; off > 0; off >>= 1) {
        s  += __shfl_xor_sync(0xffffffffu, s,  off);
        sq += __shfl_xor_sync(0xffffffffu, sq, off);
    }
    __shared__ float ws[8], wsq[8];
    __shared__ float s_mean, s_rstd;
    const int wid = tid >> 5, lane = tid & 31;
    if (lane == 0) { ws[wid] = s; wsq[wid] = sq; }
    __syncthreads();
    if (tid == 0) {
        float ts = 0.f, tsq = 0.f;
        #pragma unroll
        for (int i = 0; i < 8; i++) { ts += ws[i]; tsq += wsq[i]; }
        float mean = ts * (1.0f / EE);
        float var  = tsq * (1.0f / EE) - mean * mean;
        s_mean = mean;
        s_rstd = rsqrtf(var + LN_EPS);
    }
    __syncthreads();
    const float mean = s_mean, rstd = s_rstd;
    float4 gg = ((const float4*)g)[tid];
    float4 bb = ((const float4*)b)[tid];
    float o0 = (v.x - mean) * rstd * gg.x + bb.x;
    float o1 = (v.y - mean) * rstd * gg.y + bb.y;
    float o2 = (v.z - mean) * rstd * gg.z + bb.z;
    float o3 = (v.w - mean) * rstd * gg.w + bb.w;
    __half2* hp = (__half2*)(y + (size_t)row * EE + tid * 4);
    hp[0] = __halves2half2(__float2half(o0), __float2half(o1));
    hp[1] = __halves2half2(__float2half(o2), __float2half(o3));
}

// ======================= mma.sync single-pass FP16 GEMM, K-chunk 64 =======================
// C[M,N] = epi(fp16(A)[M,K] @ fp16(W)[N,K]^T + bias (+R))
// CTA 128x128, 8 warps (2x4), warp tile 64x32, K-chunk 64, 3-stage cp.async ring (96KB).
#define STAGE_BYTES 32768
#define OFF_A 0
#define OFF_B 16384
#define GEMM_SMEM (3*STAGE_BYTES)

// 128B rows (64 halfs), 8 chunks of 16B, XOR-swizzled by row&7
__device__ __forceinline__ uint32_t swz(int row, int c) {
    return (uint32_t)(row * 128 + ((c ^ (row & 7)) << 4));
}

// Mainloop shared by both GEMM kernels. Requires smem_u, gA, gB, K, tid, lane,
// warp_m, warp_n in scope.
#define GEMM_MAINLOOP(ACC)                                                              \
    const int nc = K >> 6;                                                              \
    auto issue_stage = [&](int c) {                                                     \
        if (c < nc) {                                                                   \
            const uint32_t sb = smem_u + (c % 3) * STAGE_BYTES;                         \
            const int k0 = c * 64;                                                      \
            _Pragma("unroll")                                                           \
            for (int j = 0; j < 4; j++) {                                               \
                const int id = tid + j * 256;                                           \
                const int row = id >> 3, cc = id & 7;                                   \
                const uint32_t so = swz(row, cc);                                       \
                const size_t go = (size_t)row * K + k0 + cc * 8;                        \
                cp_async16(sb + OFF_A + so, gA + go);                                   \
                cp_async16(sb + OFF_B + so, gB + go);                                   \
            }                                                                           \
        }                                                                               \
        cp_commit();                                                                    \
    };                                                                                  \
    issue_stage(0); issue_stage(1);                                                     \
    const int lm_r = ((lane >> 3) & 1) * 8 + (lane & 7);                                \
    const int lm_c = lane >> 4;                                                         \
    for (int c = 0; c < nc; c++) {                                                      \
        cp_wait<1>();                                                                   \
        __syncthreads();                                                                \
        issue_stage(c + 2);                                                             \
        const uint32_t sb = smem_u + (c % 3) * STAGE_BYTES;                             \
        _Pragma("unroll")                                                               \
        for (int s = 0; s < 4; s++) {                                                   \
            const int chunk = 2 * s + lm_c;                                             \
            uint32_t Bf[2][4];                                                          \
            _Pragma("unroll")                                                           \
            for (int p = 0; p < 2; p++) {                                               \
                const int row = warp_n + p * 16 + lm_r;                                 \
                ldmatrix_x4(Bf[p], sb + OFF_B + swz(row, chunk));                       \
            }                                                                           \
            _Pragma("unroll")                                                           \
            for (int mi = 0; mi < 4; mi++) {                                            \
                const int row = warp_m + mi * 16 + lm_r;                                \
                uint32_t Af[4];                                                         \
                ldmatrix_x4(Af, sb + OFF_A + swz(row, chunk));                          \
                _Pragma("unroll")                                                       \
                for (int ni = 0; ni < 4; ni++) {                                        \
                    const int p = ni >> 1, q = ni & 1;                                  \
                    mma16816(ACC[mi][ni], Af, Bf[p][q], Bf[p][2 + q]);                  \
                }                                                                       \
            }                                                                           \
        }                                                                               \
    }

template<int EPI, int OUT>   // EPI: 0 none, 2 relu, 3 +residual ; OUT: 0 fp32, 1 fp16
__global__ void __launch_bounds__(256, 2)
gemm1fp(const __half* __restrict__ Aa, const __half* __restrict__ Bw,
        const float* __restrict__ bias, const float* __restrict__ Rres,
        float* __restrict__ Cf, __half* __restrict__ Ch,
        int M, int N, int K)
{
    extern __shared__ __align__(128) char smem[];
    const uint32_t smem_u = smem_to_u32(smem);

    const int tid = threadIdx.x;
    const int wid = tid >> 5, lane = tid & 31;
    const int bm = blockIdx.y, bn = blockIdx.x;
    const int warp_m = (wid >> 2) * 64;
    const int warp_n = (wid & 3) * 32;

    const __half* gA = Aa + (size_t)(bm * 128) * K;
    const __half* gB = Bw + (size_t)(bn * 128) * K;

    float acc[4][4][4];
    #pragma unroll
    for (int i = 0; i < 4; i++)
        #pragma unroll
        for (int j = 0; j < 4; j++)
            #pragma unroll
            for (int t = 0; t < 4; t++) acc[i][j][t] = 0.f;

    GEMM_MAINLOOP(acc)

    // ---------------- epilogue ----------------
    const int g = lane >> 2, tig = lane & 3;
    #pragma unroll
    for (int ni = 0; ni < 4; ni++) {
        const int n = bn * 128 + warp_n + ni * 8 + tig * 2;
        const float b0 = __ldg(bias + n), b1 = __ldg(bias + n + 1);
        #pragma unroll
        for (int mi = 0; mi < 4; mi++) {
            const int m0 = bm * 128 + warp_m + mi * 16 + g;
            #pragma unroll
            for (int half = 0; half < 2; half++) {
                const int m = m0 + half * 8;
                float v0 = acc[mi][ni][half * 2 + 0] + b0;
                float v1 = acc[mi][ni][half * 2 + 1] + b1;
                if (EPI == 2) { v0 = fmaxf(v0, 0.f); v1 = fmaxf(v1, 0.f); }
                else if (EPI == 3) {
                    const float2 rv = *(const float2*)(Rres + (size_t)m * N + n);
                    v0 += rv.x; v1 += rv.y;
                }
                if (OUT == 0) {
                    *(float2*)(Cf + (size_t)m * N + n) = make_float2(v0, v1);
                } else {
                    *(__half2*)(Ch + (size_t)m * N + n) =
                        __halves2half2(__float2half(v0), __float2half(v1));
                }
            }
        }
    }
}

// ---- fused QKV GEMM: bnL in [0,24); w = bnL>>3 selects Wq/Wk/Wv; elu+1 on q,k; fp16 out ----
__global__ void __launch_bounds__(256, 2)
gemm_qkv(const __half* __restrict__ Aa,
         const __half* __restrict__ wq, const __half* __restrict__ wk,
         const __half* __restrict__ wv,
         const float* __restrict__ bqp, const float* __restrict__ bkp,
         const float* __restrict__ bvp,
         __half* __restrict__ oq, __half* __restrict__ ok, __half* __restrict__ ov)
{
    extern __shared__ __align__(128) char smem[];
    const uint32_t smem_u = smem_to_u32(smem);
    const int K = EE, N = EE;

    const int tid = threadIdx.x;
    const int wid = tid >> 5, lane = tid & 31;
    const int bm = blockIdx.y, bnL = blockIdx.x;
    const int w = bnL >> 3, bn = bnL & 7;
    const int warp_m = (wid >> 2) * 64;
    const int warp_n = (wid & 3) * 32;

    const __half* Bw = (w == 0) ? wq : (w == 1) ? wk : wv;
    const float* bias = (w == 0) ? bqp : (w == 1) ? bkp : bvp;
    __half* Ch = (w == 0) ? oq : (w == 1) ? ok : ov;
    const bool do_elu = (w < 2);

    const __half* gA = Aa + (size_t)(bm * 128) * K;
    const __half* gB = Bw + (size_t)(bn * 128) * K;

    float acc[4][4][4];
    #pragma unroll
    for (int i = 0; i < 4; i++)
        #pragma unroll
        for (int j = 0; j < 4; j++)
            #pragma unroll
            for (int t = 0; t < 4; t++) acc[i][j][t] = 0.f;

    GEMM_MAINLOOP(acc)

    const int g = lane >> 2, tig = lane & 3;
    #pragma unroll
    for (int ni = 0; ni < 4; ni++) {
        const int n = bn * 128 + warp_n + ni * 8 + tig * 2;
        const float b0 = __ldg(bias + n), b1 = __ldg(bias + n + 1);
        #pragma unroll
        for (int mi = 0; mi < 4; mi++) {
            const int m0 = bm * 128 + warp_m + mi * 16 + g;
            #pragma unroll
            for (int half = 0; half < 2; half++) {
                const int m = m0 + half * 8;
                float v0 = acc[mi][ni][half * 2 + 0] + b0;
                float v1 = acc[mi][ni][half * 2 + 1] + b1;
                if (do_elu) {
                    v0 = (v0 > 0.f) ? (v0 + 1.f) : expf(v0);
                    v1 = (v1 > 0.f) ? (v1 + 1.f) : expf(v1);
                }
                *(__half2*)(Ch + (size_t)m * N + n) =
                    __halves2half2(__float2half(v0), __float2half(v1));
            }
        }
    }
}

// ======================= attention stage 1: partial KV over 4 L-slices (fp16 in) ==============
__global__ void __launch_bounds__(256)
attn_kv_kernel(const __half* __restrict__ Kh, const __half* __restrict__ Vh,
               float* __restrict__ KVp, float* __restrict__ Ksp)
{
    const int bh = blockIdx.x;
    const int part = blockIdx.y;
    const int b = bh >> 4, h = bh & 15;
    __shared__ float Ks[64][68];
    __shared__ float Vs[64][68];
    const int tid = threadIdx.x;
    const int d0 = (tid >> 4) * 4, m0 = (tid & 15) * 4;

    float acc[4][4];
    #pragma unroll
    for (int i = 0; i < 4; i++)
        #pragma unroll
        for (int j = 0; j < 4; j++) acc[i][j] = 0.f;
    float ksacc = 0.f;

    const size_t base0 = ((size_t)b * LL) * EE + h * DD;
    const int s_begin = part * (LL / 4), s_end = s_begin + LL / 4;

    for (int s0 = s_begin; s0 < s_end; s0 += 64) {
        #pragma unroll
        for (int j = 0; j < 4; j++) {
            const int id = tid + j * 256;
            const int r = id >> 4, c4 = id & 15;
            const size_t ga = base0 + (size_t)(s0 + r) * EE + c4 * 4;
            const __half2* kp = (const __half2*)(Kh + ga);
            const __half2* vp = (const __half2*)(Vh + ga);
            float2 k01 = __half22float2(kp[0]), k23 = __half22float2(kp[1]);
            float2 v01 = __half22float2(vp[0]), v23 = __half22float2(vp[1]);
            Ks[r][c4*4+0]=k01.x; Ks[r][c4*4+1]=k01.y; Ks[r][c4*4+2]=k23.x; Ks[r][c4*4+3]=k23.y;
            Vs[r][c4*4+0]=v01.x; Vs[r][c4*4+1]=v01.y; Vs[r][c4*4+2]=v23.x; Vs[r][c4*4+3]=v23.y;
        }
        __syncthreads();

        if (tid < 64) {
            #pragma unroll 8
            for (int s = 0; s < 64; s++) ksacc += Ks[s][tid];
        }
        #pragma unroll 4
        for (int s = 0; s < 64; s++) {
            float4 kd = *(const float4*)&Ks[s][d0];
            float4 vm = *(const float4*)&Vs[s][m0];
            float ka[4] = {kd.x, kd.y, kd.z, kd.w};
            float va[4] = {vm.x, vm.y, vm.z, vm.w};
            #pragma unroll
            for (int i = 0; i < 4; i++)
                #pragma unroll
                for (int j = 0; j < 4; j++)
                    acc[i][j] += ka[i] * va[j];
        }
        __syncthreads();
    }

    float* kvdst = KVp + ((size_t)(part * (BB*HH) + bh) * DD) * DD;
    #pragma unroll
    for (int i = 0; i < 4; i++)
        *(float4*)(kvdst + (size_t)(d0 + i) * DD + m0) =
            make_float4(acc[i][0], acc[i][1], acc[i][2], acc[i][3]);
    if (tid < 64) Ksp[(part * (BB*HH) + bh) * DD + tid] = ksacc;
}

// ======================= attention stage 2 (fp16 Q in; sums partials; fp16 out) ===============
__global__ void __launch_bounds__(256)
attn_out_kernel(const __half* __restrict__ Qh, const float* __restrict__ KVp,
                const float* __restrict__ Ksp, __half* __restrict__ Oh)
{
    const int bh = blockIdx.y;
    const int b = bh >> 4, h = bh & 15;
    const int tid = threadIdx.x;
    __shared__ float KVs[64][64];
    __shared__ float ks[64];

    #pragma unroll
    for (int j = 0; j < 4; j++) {
        const int id = tid + j * 256;
        float4 a = make_float4(0.f, 0.f, 0.f, 0.f);
        #pragma unroll
        for (int part = 0; part < 4; part++) {
            float4 p = ((const float4*)(KVp + (size_t)(part * (BB*HH) + bh) * DD * DD))[id];
            a.x += p.x; a.y += p.y; a.z += p.z; a.w += p.w;
        }
        ((float4*)&KVs[0][0])[id] = a;
    }
    if (tid < 16) {
        float4 a = make_float4(0.f, 0.f, 0.f, 0.f);
        #pragma unroll
        for (int part = 0; part < 4; part++) {
            float4 p = ((const float4*)(Ksp + (part * (BB*HH) + bh) * DD))[tid];
            a.x += p.x; a.y += p.y; a.z += p.z; a.w += p.w;
        }
        ((float4*)ks)[tid] = a;
    }
    __syncthreads();

    const int row = b * LL + blockIdx.x * 256 + tid;
    const __half2* qrow = (const __half2*)(Qh + (size_t)row * EE + h * DD);

    float qf[64];
    #pragma unroll
    for (int d2 = 0; d2 < 32; d2++) {
        float2 f = __half22float2(qrow[d2]);
        qf[d2*2] = f.x; qf[d2*2+1] = f.y;
    }

    float z = 0.f;
    #pragma unroll
    for (int d = 0; d < 64; d++) z += qf[d] * ks[d];
    const float zi = 1.0f / (z + ATTN_EPS);

    float acc[64];
    #pragma unroll
    for (int j = 0; j < 64; j++) acc[j] = 0.f;

    #pragma unroll 4
    for (int d = 0; d < 64; d++) {
        const float qd = qf[d];
        const float4* kvr = (const float4*)&KVs[d][0];
        #pragma unroll
        for (int j4 = 0; j4 < 16; j4++) {
            float4 kv = kvr[j4];
            acc[j4*4+0] += qd * kv.x;
            acc[j4*4+1] += qd * kv.y;
            acc[j4*4+2] += qd * kv.z;
            acc[j4*4+3] += qd * kv.w;
        }
    }

    __half* hp = Oh + (size_t)row * EE + h * DD;
    #pragma unroll
    for (int j2 = 0; j2 < 32; j2++) {
        ((__half2*)hp)[j2] = __halves2half2(
            __float2half(acc[j2*2]   * zi),
            __float2half(acc[j2*2+1] * zi));
    }
}

// ======================= host launcher =======================
extern "C" void kernel_launch(void* const* d_in, const int* in_sizes, int n_in,
                              void* d_out, int out_size)
{
    const float* x     = (const float*)d_in[0];
    const float* ln1_g = (const float*)d_in[1];
    const float* ln1_b = (const float*)d_in[2];
    const float* ln2_g = (const float*)d_in[3];
    const float* ln2_b = (const float*)d_in[4];
    const float* Wq = (const float*)d_in[5];  const float* bq = (const float*)d_in[6];
    const float* Wk = (const float*)d_in[7];  const float* bk = (const float*)d_in[8];
    const float* Wv = (const float*)d_in[9];  const float* bv = (const float*)d_in[10];
    const float* Wo = (const float*)d_in[11]; const float* bo = (const float*)d_in[12];
    const float* W1 = (const float*)d_in[13]; const float* b1 = (const float*)d_in[14];
    const float* W2 = (const float*)d_in[15]; const float* b2 = (const float*)d_in[16];
    float* out = (float*)d_out;

    #define SYM(T, name, sym) T* name; { void* p; cudaGetSymbolAddress(&p, sym); name = (T*)p; }
    SYM(__half, h, g_h)  SYM(__half, ao, g_ao)  SYM(__half, f1, g_f1)
    SYM(__half, q, g_q)  SYM(__half, k, g_k)  SYM(__half, v, g_v)
    SYM(float, x2, g_x2)
    SYM(__half, wq, g_wq) SYM(__half, wk, g_wk) SYM(__half, wv, g_wv)
    SYM(__half, wo, g_wo) SYM(__half, w1, g_w1) SYM(__half, w2, g_w2)
    SYM(float, kvp, g_kvp) SYM(float, ksp, g_ksp)
    #undef SYM

    cudaFuncSetAttribute(gemm_qkv,     cudaFuncAttributeMaxDynamicSharedMemorySize, GEMM_SMEM);
    cudaFuncSetAttribute(gemm1fp<3,0>, cudaFuncAttributeMaxDynamicSharedMemorySize, GEMM_SMEM);
    cudaFuncSetAttribute(gemm1fp<2,1>, cudaFuncAttributeMaxDynamicSharedMemorySize, GEMM_SMEM);

    // 1. fused weight conversion (single launch)
    const int total4 = 4 * NE4 + 2 * NF4;
    cvt_all_kernel<<<total4 / 256, 256>>>(Wq, Wk, Wv, Wo, W1, W2,
        wq, wk, wv, wo, w1, w2);
    // 2. LN1 -> h (fp16)
    ln_fp16_kernel<<<MM, 256>>>(x, ln1_g, ln1_b, h);
    // 3. fused QKV projection (elu+1 on q,k; fp16 out)
    gemm_qkv<<<dim3(24, MM / 128), 256, GEMM_SMEM>>>(h,
        wq, wk, wv, bq, bk, bv, q, k, v);
    // 4. linear attention
    attn_kv_kernel<<<dim3(BB * HH, 4), 256>>>(k, v, kvp, ksp);
    attn_out_kernel<<<dim3(LL / 256, BB * HH), 256>>>(q, kvp, ksp, ao);
    // 5. Wo projection + residual -> x2
    gemm1fp<3,0><<<dim3(EE / 128, MM / 128), 256, GEMM_SMEM>>>(ao, wo,
        bo, x, x2, nullptr, MM, EE, EE);
    // 6. LN2 -> h (fp16, reuse)
    ln_fp16_kernel<<<MM, 256>>>(x2, ln2_g, ln2_b, h);
    // 7. FFN
    gemm1fp<2,1><<<dim3(FF / 128, MM / 128), 256, GEMM_SMEM>>>(h, w1,
        b1, nullptr, nullptr, f1, MM, FF, EE);
    gemm1fp<3,0><<<dim3(EE / 128, MM / 128), 256, GEMM_SMEM>>>(f1, w2,
        b2, x2, out, nullptr, MM, EE, FF);
}